// round 4
// baseline (speedup 1.0000x reference)
#include <cuda_runtime.h>
#include <math.h>

#define NSEQ 2048
#define CDIM 1024
#define HH 16
#define DD 64
#define FDIM 3072

// ---------------- scratch (static device allocations; no cudaMalloc) --------
__device__ float g_qkv[NSEQ * FDIM];
__device__ float g_qn[HH * NSEQ * DD];
__device__ float g_kn[HH * NSEQ * DD];
__device__ float g_v [HH * NSEQ * DD];
__device__ float g_S [67108864];               // 16*2048*2048 fp32 = 256 MB
__device__ float g_m [HH * NSEQ];
__device__ float g_l [HH * NSEQ];
__device__ float g_oa[NSEQ * CDIM];
__device__ float g_sumv[HH * DD];

// ---------------- C = A * B^T, 128x64x16 tile, 8x4 micro-tile ---------------
// A: M x K row-major, B: N x K row-major, C: M x N row-major.
__global__ __launch_bounds__(256) void gemm2(
    const float* __restrict__ A, const float* __restrict__ B,
    float* __restrict__ C, int M, int Nn, int K)
{
    __shared__ float As[16][130];
    __shared__ float Bs[16][66];
    int bm = blockIdx.y, bn = blockIdx.x;
    int tid = threadIdx.x;
    int tx = tid & 15, ty = tid >> 4;

    const float* Ab = A + (size_t)bm * 128 * K;
    const float* Bb = B + (size_t)bn * 64 * K;

    float acc[8][4] = {};
    for (int k0 = 0; k0 < K; k0 += 16) {
        #pragma unroll
        for (int l = 0; l < 8; l++) {
            int idx = tid + l * 256;
            int kk = idx & 15, m = idx >> 4;
            As[kk][m] = Ab[(size_t)m * K + k0 + kk];
        }
        #pragma unroll
        for (int l = 0; l < 4; l++) {
            int idx = tid + l * 256;
            int kk = idx & 15, n = idx >> 4;
            Bs[kk][n] = Bb[(size_t)n * K + k0 + kk];
        }
        __syncthreads();
        #pragma unroll
        for (int kk = 0; kk < 16; kk++) {
            float a[8], b[4];
            #pragma unroll
            for (int i = 0; i < 8; i++) a[i] = As[kk][ty * 8 + i];
            #pragma unroll
            for (int c = 0; c < 4; c++) b[c] = Bs[kk][tx * 4 + c];
            #pragma unroll
            for (int i = 0; i < 8; i++)
                #pragma unroll
                for (int c = 0; c < 4; c++)
                    acc[i][c] = fmaf(a[i], b[c], acc[i][c]);
        }
        __syncthreads();
    }
    #pragma unroll
    for (int i = 0; i < 8; i++) {
        float4 o = make_float4(acc[i][0], acc[i][1], acc[i][2], acc[i][3]);
        *reinterpret_cast<float4*>(
            &C[(size_t)(bm * 128 + ty * 8 + i) * Nn + bn * 64 + tx * 4]) = o;
    }
}

// ---------------- split qkv, l2-normalize q/k, emit kv outputs -------------
__global__ void split_norm(float* __restrict__ kout, float* __restrict__ vout)
{
    int n = blockIdx.x, h = blockIdx.y, d = threadIdx.x;   // 64 threads
    int base = n * FDIM + (h * DD + d) * 3;
    float q = g_qkv[base + 0];
    float k = g_qkv[base + 1];
    float v = g_qkv[base + 2];

    float sq = q * q, sk = k * k;
    #pragma unroll
    for (int off = 16; off > 0; off >>= 1) {
        sq += __shfl_xor_sync(0xffffffffu, sq, off);
        sk += __shfl_xor_sync(0xffffffffu, sk, off);
    }
    __shared__ float red[4];
    int w = d >> 5, lane = d & 31;
    if (lane == 0) { red[w] = sq; red[2 + w] = sk; }
    __syncthreads();
    float nq = sqrtf(red[0] + red[1]);
    float nk = sqrtf(red[2] + red[3]);

    int o = (h * NSEQ + n) * DD + d;
    g_qn[o] = q / fmaxf(nq, 1e-12f);
    g_kn[o] = k / fmaxf(nk, 1e-12f);
    kout[o] = k;
    vout[o] = v;
    g_v[o]  = v;
}

// ---------------- sum of V over sequence (for b_post term) -----------------
__global__ void sumv_k()
{
    int g = blockIdx.x, d = threadIdx.x;
    float s = 0.f;
    for (int j = 0; j < NSEQ; j++) s += g_v[(g * NSEQ + j) * DD + d];
    g_sumv[g * DD + d] = s;
}

// ---------------- fused scores: cosine dots + temp + pre-mix + pos_bias ----
// CTA = 32x32 causal (i,j) tile, 256 thr: thread owns 4 i-rows x 1 j-col.
// Inner product vectorized over d with float4 smem loads.
__global__ __launch_bounds__(256) void scores_k(
    const float* __restrict__ Wpre, const float* __restrict__ bpre,
    const float* __restrict__ pb, const float* __restrict__ temp_p)
{
    int it = blockIdx.y, jt = blockIdx.x;
    if (jt > it) return;

    __shared__ float qs[32][68];
    __shared__ float ks[32][68];
    __shared__ float wpre_s[256];
    __shared__ float bpre_s[16];

    int tid = threadIdx.x;
    wpre_s[tid] = Wpre[tid];
    if (tid < 16) bpre_s[tid] = bpre[tid];

    float temp = __ldg(temp_p);
    int tx = tid & 31;        // j within tile
    int ty = tid >> 5;        // i-group (4 rows)
    int i0 = it * 32, j0 = jt * 32;

    float raw[16][4];
    #pragma unroll 1
    for (int h = 0; h < 16; h++) {
        __syncthreads();
        #pragma unroll
        for (int l = 0; l < 8; l++) {
            int idx = tid + l * 256;
            int r = idx >> 6, d = idx & 63;
            qs[r][d] = g_qn[(h * NSEQ + i0 + r) * DD + d];
            ks[r][d] = g_kn[(h * NSEQ + j0 + r) * DD + d];
        }
        __syncthreads();
        float r0 = 0.f, r1 = 0.f, r2 = 0.f, r3 = 0.f;
        #pragma unroll
        for (int kb = 0; kb < 64; kb += 4) {
            float4 k4 = *reinterpret_cast<const float4*>(&ks[tx][kb]);
            float4 q;
            q = *reinterpret_cast<const float4*>(&qs[ty * 4 + 0][kb]);
            r0 = fmaf(q.x, k4.x, r0); r0 = fmaf(q.y, k4.y, r0);
            r0 = fmaf(q.z, k4.z, r0); r0 = fmaf(q.w, k4.w, r0);
            q = *reinterpret_cast<const float4*>(&qs[ty * 4 + 1][kb]);
            r1 = fmaf(q.x, k4.x, r1); r1 = fmaf(q.y, k4.y, r1);
            r1 = fmaf(q.z, k4.z, r1); r1 = fmaf(q.w, k4.w, r1);
            q = *reinterpret_cast<const float4*>(&qs[ty * 4 + 2][kb]);
            r2 = fmaf(q.x, k4.x, r2); r2 = fmaf(q.y, k4.y, r2);
            r2 = fmaf(q.z, k4.z, r2); r2 = fmaf(q.w, k4.w, r2);
            q = *reinterpret_cast<const float4*>(&qs[ty * 4 + 3][kb]);
            r3 = fmaf(q.x, k4.x, r3); r3 = fmaf(q.y, k4.y, r3);
            r3 = fmaf(q.z, k4.z, r3); r3 = fmaf(q.w, k4.w, r3);
        }
        raw[h][0] = r0 * temp; raw[h][1] = r1 * temp;
        raw[h][2] = r2 * temp; raw[h][3] = r3 * temp;
    }

    int jg = j0 + tx;
    #pragma unroll 1
    for (int g = 0; g < 16; g++) {
        #pragma unroll
        for (int ii = 0; ii < 4; ii++) {
            float acc = bpre_s[g];
            #pragma unroll
            for (int h = 0; h < 16; h++)
                acc = fmaf(wpre_s[g * 16 + h], raw[h][ii], acc);
            int i = i0 + ty * 4 + ii;
            size_t idx = ((size_t)(g * NSEQ + i)) * NSEQ + jg;
            g_S[idx] = acc + pb[idx];
        }
    }
}

// ---------------- per-row online max / sum-exp ------------------------------
__global__ __launch_bounds__(256) void rowstat_k()
{
    int i = blockIdx.x, g = blockIdx.y;
    const float* row = g_S + ((size_t)(g * NSEQ + i)) * NSEQ;
    int tid = threadIdx.x;

    float m = -INFINITY, l = 0.f;
    for (int j = tid; j <= i; j += 256) {
        float s = row[j];
        float nm = fmaxf(m, s);
        l = l * __expf(m - nm) + __expf(s - nm);
        m = nm;
    }
    __shared__ float sm[256], sl[256];
    sm[tid] = m; sl[tid] = l;
    __syncthreads();
    for (int s = 128; s > 0; s >>= 1) {
        if (tid < s) {
            float m1 = sm[tid], l1 = sl[tid];
            float m2 = sm[tid + s], l2 = sl[tid + s];
            float M = fmaxf(m1, m2);
            float L = (M == -INFINITY) ? 0.f
                      : l1 * __expf(m1 - M) + l2 * __expf(m2 - M);
            sm[tid] = M; sl[tid] = L;
        }
        __syncthreads();
    }
    if (tid == 0) { g_m[g * NSEQ + i] = sm[0]; g_l[g * NSEQ + i] = sl[0]; }
}

// ---------------- softmax normalize + talking-heads post-mix (in place) ----
__global__ __launch_bounds__(256) void postmix_k(const float* __restrict__ Wpost)
{
    __shared__ float w[256];
    int tid = threadIdx.x;
    w[tid] = Wpost[tid];
    int i = blockIdx.y;
    int j = blockIdx.x * 256 + tid;
    __syncthreads();
    if (j > i) return;

    float a[16];
    #pragma unroll
    for (int h = 0; h < 16; h++) {
        size_t idx = ((size_t)(h * NSEQ + i)) * NSEQ + j;
        float s = g_S[idx];
        a[h] = __expf(s - g_m[h * NSEQ + i]) / g_l[h * NSEQ + i];
    }
    #pragma unroll
    for (int g = 0; g < 16; g++) {
        float val = 0.f;
        #pragma unroll
        for (int h = 0; h < 16; h++) val = fmaf(w[g * 16 + h], a[h], val);
        g_S[((size_t)(g * NSEQ + i)) * NSEQ + j] = val;
    }
}

// ---------------- causal attn @ V  →  oa[n][(g d)] --------------------------
// Same 128x64x16 / 8x4 structure as gemm2; mask folded into S-tile load.
__global__ __launch_bounds__(256) void av_k(const float* __restrict__ bpost)
{
    int it = blockIdx.x, g = blockIdx.y;
    __shared__ float Ssm[16][130];
    __shared__ float Vsm[16][66];
    int tid = threadIdx.x;
    int tx = tid & 15, ty = tid >> 4;
    int i0 = it * 128;

    float acc[8][4] = {};
    for (int j0 = 0; j0 < i0 + 128; j0 += 16) {
        #pragma unroll
        for (int l = 0; l < 8; l++) {
            int idx = tid + l * 256;
            int kk = idx & 15, m = idx >> 4;
            int j = j0 + kk, i = i0 + m;
            Ssm[kk][m] = (j <= i)
                ? g_S[((size_t)(g * NSEQ + i)) * NSEQ + j] : 0.f;
        }
        #pragma unroll
        for (int l = 0; l < 4; l++) {
            int idx = tid + l * 256;
            int n = idx & 63, kk = idx >> 6;
            Vsm[kk][n] = g_v[(g * NSEQ + j0 + kk) * DD + n];
        }
        __syncthreads();
        #pragma unroll
        for (int kk = 0; kk < 16; kk++) {
            float a[8], b[4];
            #pragma unroll
            for (int i = 0; i < 8; i++) a[i] = Ssm[kk][ty * 8 + i];
            #pragma unroll
            for (int c = 0; c < 4; c++) b[c] = Vsm[kk][tx * 4 + c];
            #pragma unroll
            for (int i = 0; i < 8; i++)
                #pragma unroll
                for (int c = 0; c < 4; c++)
                    acc[i][c] = fmaf(a[i], b[c], acc[i][c]);
        }
        __syncthreads();
    }
    float bp = bpost[g];
    #pragma unroll
    for (int i = 0; i < 8; i++) {
        float4 o;
        int d = tx * 4;
        o.x = acc[i][0] + bp * g_sumv[g * DD + d + 0];
        o.y = acc[i][1] + bp * g_sumv[g * DD + d + 1];
        o.z = acc[i][2] + bp * g_sumv[g * DD + d + 2];
        o.w = acc[i][3] + bp * g_sumv[g * DD + d + 3];
        *reinterpret_cast<float4*>(
            &g_oa[(size_t)(i0 + ty * 8 + i) * CDIM + g * DD + d]) = o;
    }
}

// ---------------- launch -----------------------------------------------------
extern "C" void kernel_launch(void* const* d_in, const int* in_sizes, int n_in,
                              void* d_out, int out_size)
{
    const float* x     = (const float*)d_in[0];
    const float* pb    = (const float*)d_in[1];
    // d_in[2] = mask: causal, applied analytically
    const float* Wqkv  = (const float*)d_in[3];
    const float* Wout  = (const float*)d_in[4];
    const float* temp  = (const float*)d_in[5];
    const float* Wpre  = (const float*)d_in[6];
    const float* bpre  = (const float*)d_in[7];
    const float* Wpost = (const float*)d_in[8];
    const float* bpost = (const float*)d_in[9];

    float* out  = (float*)d_out;                 // [2048, 1024]
    float* kout = out + NSEQ * CDIM;             // kv[0] = k  [16,2048,64]
    float* vout = kout + HH * NSEQ * DD;         // kv[1] = v

    void *p_qkv, *p_oa;
    cudaGetSymbolAddress(&p_qkv, g_qkv);
    cudaGetSymbolAddress(&p_oa,  g_oa);

    // 1. qkv = x @ W_qkv^T
    gemm2<<<dim3(FDIM / 64, NSEQ / 128), 256>>>(x, Wqkv, (float*)p_qkv,
                                                NSEQ, FDIM, CDIM);
    // 2. split + l2norm + kv outputs
    split_norm<<<dim3(NSEQ, HH), 64>>>(kout, vout);
    // 3. sum_j v  (b_post term)
    sumv_k<<<HH, DD>>>();
    // 4. scores: dots*temp -> pre-mix -> +pos_bias (causal tiles only)
    scores_k<<<dim3(64, 64), 256>>>(Wpre, bpre, pb, temp);
    // 5. row max / sum-exp
    rowstat_k<<<dim3(NSEQ, HH), 256>>>();
    // 6. softmax + post-mix (in place)
    postmix_k<<<dim3(NSEQ / 256, NSEQ), 256>>>(Wpost);
    // 7. attn @ V  (+ b_post * sum v)
    av_k<<<dim3(NSEQ / 128, HH), 256>>>(bpost);
    // 8. out = oa @ W_out^T
    gemm2<<<dim3(CDIM / 64, NSEQ / 128), 256>>>((const float*)p_oa, Wout, out,
                                                NSEQ, CDIM, CDIM);
}

// round 7
// speedup vs baseline: 1.8598x; 1.8598x over previous
#include <cuda_runtime.h>
#include <cuda_bf16.h>
#include <math.h>
#include <cstdint>

#define NSEQ 2048
#define CDIM 1024
#define HH 16
#define DD 64
#define FDIM 3072

// ---------------- scratch (static device allocations; no cudaMalloc) --------
__device__ float g_qkv[NSEQ * FDIM];
__device__ float g_qn[HH * NSEQ * DD];
__device__ float g_kn[HH * NSEQ * DD];
__device__ float g_v [HH * NSEQ * DD];
__device__ float g_S [67108864];               // 16*2048*2048 fp32 = 256 MB
__device__ float g_m [HH * NSEQ];
__device__ float g_l [HH * NSEQ];
__device__ float g_oa[NSEQ * CDIM];
__device__ float g_sumv[HH * DD];

// bf16 hi/lo split buffers for tensor-core GEMMs
__device__ __nv_bfloat16 g_xhi[NSEQ * CDIM],  g_xlo[NSEQ * CDIM];
__device__ __nv_bfloat16 g_whi[FDIM * CDIM],  g_wlo[FDIM * CDIM];
__device__ __nv_bfloat16 g_ohi[CDIM * CDIM],  g_olo[CDIM * CDIM];   // W_out
__device__ __nv_bfloat16 g_ahi[NSEQ * CDIM],  g_alo[NSEQ * CDIM];   // oa

// ---------------- fp32 -> bf16 hi/lo split ----------------------------------
__global__ __launch_bounds__(256) void conv_split(
    const float* __restrict__ in, __nv_bfloat16* __restrict__ hi,
    __nv_bfloat16* __restrict__ lo, int n)
{
    int i = blockIdx.x * 256 + threadIdx.x;
    if (i >= n) return;
    float x = in[i];
    __nv_bfloat16 h = __float2bfloat16(x);
    hi[i] = h;
    lo[i] = __float2bfloat16(x - __bfloat162float(h));
}

// ---------------- warp-MMA bf16x3 GEMM: C[M,Nn] = A[M,K] * B[Nn,K]^T --------
// mma.sync m16n8k16 row.col, fp32 accum. 256 thr = 8 warps, tile 128x64,
// warp tile 32x32, BK=16. Smem rows padded to 24 bf16 (conflict-free frags).
__device__ __forceinline__ void mma_bf16(float* c, const uint32_t* a,
                                         const uint32_t* b)
{
    asm volatile(
        "mma.sync.aligned.m16n8k16.row.col.f32.bf16.bf16.f32 "
        "{%0,%1,%2,%3}, {%4,%5,%6,%7}, {%8,%9}, {%0,%1,%2,%3};"
        : "+f"(c[0]), "+f"(c[1]), "+f"(c[2]), "+f"(c[3])
        : "r"(a[0]), "r"(a[1]), "r"(a[2]), "r"(a[3]), "r"(b[0]), "r"(b[1]));
}

#define ASTR 24   // padded bf16 row stride

__global__ __launch_bounds__(256) void hmma_gemm(
    const __nv_bfloat16* __restrict__ Ahi, const __nv_bfloat16* __restrict__ Alo,
    const __nv_bfloat16* __restrict__ Bhi, const __nv_bfloat16* __restrict__ Blo,
    float* __restrict__ C, int K, int ldc)
{
    __shared__ __align__(16) __nv_bfloat16 Ah[128 * ASTR], Al[128 * ASTR];
    __shared__ __align__(16) __nv_bfloat16 Bh[64 * ASTR],  Bl[64 * ASTR];

    int tid = threadIdx.x, lane = tid & 31, wid = tid >> 5;
    int wm = wid & 3, wn = wid >> 2;           // warp tile: rows 32*wm, cols 32*wn
    int bm = blockIdx.y, bn = blockIdx.x;
    int tq = lane >> 2;                        // 0..7
    int tk = (lane & 3) * 2;                   // 0,2,4,6

    float acc[2][4][4] = {};

    for (int k0 = 0; k0 < K; k0 += 16) {
        // load A chunk: 128x16 bf16 per split; idx 0..511, 4 bf16 per load
        #pragma unroll
        for (int l = 0; l < 2; l++) {
            int idx = tid + l * 256;
            int r = idx >> 2, c4 = idx & 3;
            size_t g = (size_t)(bm * 128 + r) * K + k0 + c4 * 4;
            *(uint2*)&Ah[r * ASTR + c4 * 4] = *(const uint2*)(Ahi + g);
            *(uint2*)&Al[r * ASTR + c4 * 4] = *(const uint2*)(Alo + g);
        }
        // load B chunk: 64x16 bf16 per split; idx 0..255
        {
            int r = tid >> 2, c4 = tid & 3;
            size_t g = (size_t)(bn * 64 + r) * K + k0 + c4 * 4;
            *(uint2*)&Bh[r * ASTR + c4 * 4] = *(const uint2*)(Bhi + g);
            *(uint2*)&Bl[r * ASTR + c4 * 4] = *(const uint2*)(Blo + g);
        }
        __syncthreads();

        uint32_t ah[2][4], al[2][4], bh[4][2], bl[4][2];
        #pragma unroll
        for (int t = 0; t < 2; t++) {
            int m = (wm * 32 + t * 16 + tq) * ASTR;
            ah[t][0] = *(const uint32_t*)&Ah[m + tk];
            ah[t][1] = *(const uint32_t*)&Ah[m + 8 * ASTR + tk];
            ah[t][2] = *(const uint32_t*)&Ah[m + tk + 8];
            ah[t][3] = *(const uint32_t*)&Ah[m + 8 * ASTR + tk + 8];
            al[t][0] = *(const uint32_t*)&Al[m + tk];
            al[t][1] = *(const uint32_t*)&Al[m + 8 * ASTR + tk];
            al[t][2] = *(const uint32_t*)&Al[m + tk + 8];
            al[t][3] = *(const uint32_t*)&Al[m + 8 * ASTR + tk + 8];
        }
        #pragma unroll
        for (int n = 0; n < 4; n++) {
            int r = (wn * 32 + n * 8 + tq) * ASTR;
            bh[n][0] = *(const uint32_t*)&Bh[r + tk];
            bh[n][1] = *(const uint32_t*)&Bh[r + tk + 8];
            bl[n][0] = *(const uint32_t*)&Bl[r + tk];
            bl[n][1] = *(const uint32_t*)&Bl[r + tk + 8];
        }
        #pragma unroll
        for (int t = 0; t < 2; t++)
            #pragma unroll
            for (int n = 0; n < 4; n++) {
                mma_bf16(acc[t][n], ah[t], bh[n]);
                mma_bf16(acc[t][n], al[t], bh[n]);
                mma_bf16(acc[t][n], ah[t], bl[n]);
            }
        __syncthreads();
    }

    // epilogue: c0,c1 -> (row tq, cols tk..tk+1); c2,c3 -> row tq+8
    #pragma unroll
    for (int t = 0; t < 2; t++) {
        int row = bm * 128 + wm * 32 + t * 16 + tq;
        #pragma unroll
        for (int n = 0; n < 4; n++) {
            int col = bn * 64 + wn * 32 + n * 8 + tk;
            *(float2*)&C[(size_t)row * ldc + col] =
                make_float2(acc[t][n][0], acc[t][n][1]);
            *(float2*)&C[(size_t)(row + 8) * ldc + col] =
                make_float2(acc[t][n][2], acc[t][n][3]);
        }
    }
}

// ---------------- split qkv, l2-normalize q/k, emit kv outputs -------------
__global__ void split_norm(float* __restrict__ kout, float* __restrict__ vout)
{
    int n = blockIdx.x, h = blockIdx.y, d = threadIdx.x;   // 64 threads
    int base = n * FDIM + (h * DD + d) * 3;
    float q = g_qkv[base + 0];
    float k = g_qkv[base + 1];
    float v = g_qkv[base + 2];

    float sq = q * q, sk = k * k;
    #pragma unroll
    for (int off = 16; off > 0; off >>= 1) {
        sq += __shfl_xor_sync(0xffffffffu, sq, off);
        sk += __shfl_xor_sync(0xffffffffu, sk, off);
    }
    __shared__ float red[4];
    int w = d >> 5, lane = d & 31;
    if (lane == 0) { red[w] = sq; red[2 + w] = sk; }
    __syncthreads();
    float nq = sqrtf(red[0] + red[1]);
    float nk = sqrtf(red[2] + red[3]);

    int o = (h * NSEQ + n) * DD + d;
    g_qn[o] = q / fmaxf(nq, 1e-12f);
    g_kn[o] = k / fmaxf(nk, 1e-12f);
    kout[o] = k;
    vout[o] = v;
    g_v[o]  = v;
}

// ---------------- sum of V over sequence (for b_post term) -----------------
__global__ void sumv_k()
{
    int g = blockIdx.x, d = threadIdx.x;
    float s = 0.f;
    for (int j = 0; j < NSEQ; j++) s += g_v[(g * NSEQ + j) * DD + d];
    g_sumv[g * DD + d] = s;
}

// ---------------- fused scores (R1 version: known 361us) --------------------
__global__ __launch_bounds__(256) void scores_k(
    const float* __restrict__ Wpre, const float* __restrict__ bpre,
    const float* __restrict__ pb, const float* __restrict__ temp_p)
{
    int it = blockIdx.y, jt = blockIdx.x;
    if (jt > it) return;

    __shared__ float qs[32][65];
    __shared__ float ks[32][65];
    __shared__ float wpre_s[256];
    __shared__ float bpre_s[16];

    int tid = threadIdx.x;
    wpre_s[tid] = Wpre[tid];
    if (tid < 16) bpre_s[tid] = bpre[tid];

    float temp = __ldg(temp_p);
    int tx = tid & 15, ty = tid >> 4;
    int i0 = it * 32, j0 = jt * 32;

    float raw[16][4];
    #pragma unroll 1
    for (int h = 0; h < 16; h++) {
        __syncthreads();
        #pragma unroll
        for (int l = 0; l < 8; l++) {
            int idx = tid + l * 256;
            int r = idx >> 6, dd = idx & 63;
            qs[r][dd] = g_qn[(h * NSEQ + i0 + r) * DD + dd];
            ks[r][dd] = g_kn[(h * NSEQ + j0 + r) * DD + dd];
        }
        __syncthreads();
        float a00 = 0.f, a01 = 0.f, a10 = 0.f, a11 = 0.f;
        #pragma unroll 8
        for (int kk = 0; kk < 64; kk++) {
            float q0 = qs[ty * 2 + 0][kk];
            float q1 = qs[ty * 2 + 1][kk];
            float k0 = ks[tx * 2 + 0][kk];
            float k1 = ks[tx * 2 + 1][kk];
            a00 = fmaf(q0, k0, a00); a01 = fmaf(q0, k1, a01);
            a10 = fmaf(q1, k0, a10); a11 = fmaf(q1, k1, a11);
        }
        raw[h][0] = a00 * temp; raw[h][1] = a01 * temp;
        raw[h][2] = a10 * temp; raw[h][3] = a11 * temp;
    }

    int ibase = i0 + ty * 2;
    int jbase = j0 + tx * 2;
    #pragma unroll 1
    for (int g = 0; g < 16; g++) {
        #pragma unroll
        for (int e = 0; e < 4; e++) {
            float acc = bpre_s[g];
            #pragma unroll
            for (int h = 0; h < 16; h++)
                acc = fmaf(wpre_s[g * 16 + h], raw[h][e], acc);
            int ii = ibase + (e >> 1);
            int jj = jbase + (e & 1);
            size_t idx = ((size_t)(g * NSEQ + ii)) * NSEQ + jj;
            g_S[idx] = acc + pb[idx];
        }
    }
}

// ---------------- per-row online max / sum-exp ------------------------------
__global__ __launch_bounds__(256) void rowstat_k()
{
    int i = blockIdx.x, g = blockIdx.y;
    const float* row = g_S + ((size_t)(g * NSEQ + i)) * NSEQ;
    int tid = threadIdx.x;

    float m = -INFINITY, l = 0.f;
    for (int j = tid; j <= i; j += 256) {
        float s = row[j];
        float nm = fmaxf(m, s);
        l = l * __expf(m - nm) + __expf(s - nm);
        m = nm;
    }
    __shared__ float sm[256], sl[256];
    sm[tid] = m; sl[tid] = l;
    __syncthreads();
    for (int s = 128; s > 0; s >>= 1) {
        if (tid < s) {
            float m1 = sm[tid], l1 = sl[tid];
            float m2 = sm[tid + s], l2 = sl[tid + s];
            float M = fmaxf(m1, m2);
            float L = (M == -INFINITY) ? 0.f
                      : l1 * __expf(m1 - M) + l2 * __expf(m2 - M);
            sm[tid] = M; sl[tid] = L;
        }
        __syncthreads();
    }
    if (tid == 0) { g_m[g * NSEQ + i] = sm[0]; g_l[g * NSEQ + i] = sl[0]; }
}

// ---------------- softmax normalize + talking-heads post-mix (in place) ----
__global__ __launch_bounds__(256) void postmix_k(const float* __restrict__ Wpost)
{
    __shared__ float w[256];
    int tid = threadIdx.x;
    w[tid] = Wpost[tid];
    int i = blockIdx.y;
    int j = blockIdx.x * 256 + tid;
    __syncthreads();
    if (j > i) return;

    float a[16];
    #pragma unroll
    for (int h = 0; h < 16; h++) {
        size_t idx = ((size_t)(h * NSEQ + i)) * NSEQ + j;
        float s = g_S[idx];
        a[h] = __expf(s - g_m[h * NSEQ + i]) / g_l[h * NSEQ + i];
    }
    #pragma unroll
    for (int g = 0; g < 16; g++) {
        float val = 0.f;
        #pragma unroll
        for (int h = 0; h < 16; h++) val = fmaf(w[g * 16 + h], a[h], val);
        g_S[((size_t)(g * NSEQ + i)) * NSEQ + j] = val;
    }
}

// ---------------- causal attn @ V  →  oa[n][(g d)]  (R1 version) ------------
__global__ __launch_bounds__(256) void av_k(const float* __restrict__ bpost)
{
    int itile = blockIdx.x, g = blockIdx.y;
    __shared__ float Ssm[64][65];
    __shared__ float Vsm[64][64];
    int tid = threadIdx.x;
    int tx = tid & 15, ty = tid >> 4;
    int i0 = itile * 64;

    float acc[4][4] = {};
    for (int j0 = 0; j0 <= i0; j0 += 64) {
        bool diag = (j0 == i0);
        #pragma unroll
        for (int l = 0; l < 16; l++) {
            int idx = tid + l * 256;
            int r = idx >> 6, c = idx & 63;
            float s = 0.f;
            if (!diag || (j0 + c <= i0 + r))
                s = g_S[((size_t)(g * NSEQ + i0 + r)) * NSEQ + j0 + c];
            Ssm[r][c] = s;
            Vsm[r][c] = g_v[(g * NSEQ + j0 + r) * DD + c];
        }
        __syncthreads();
        #pragma unroll 8
        for (int kk = 0; kk < 64; kk++) {
            float a[4], b[4];
            #pragma unroll
            for (int i = 0; i < 4; i++) a[i] = Ssm[ty * 4 + i][kk];
            #pragma unroll
            for (int j = 0; j < 4; j++) b[j] = Vsm[kk][tx * 4 + j];
            #pragma unroll
            for (int i = 0; i < 4; i++)
                #pragma unroll
                for (int j = 0; j < 4; j++) acc[i][j] = fmaf(a[i], b[j], acc[i][j]);
        }
        __syncthreads();
    }
    float bp = bpost[g];
    #pragma unroll
    for (int i = 0; i < 4; i++)
        #pragma unroll
        for (int j = 0; j < 4; j++) {
            int d = tx * 4 + j;
            g_oa[(size_t)(i0 + ty * 4 + i) * CDIM + g * DD + d] =
                acc[i][j] + bp * g_sumv[g * DD + d];
        }
}

// ---------------- launch -----------------------------------------------------
extern "C" void kernel_launch(void* const* d_in, const int* in_sizes, int n_in,
                              void* d_out, int out_size)
{
    const float* x     = (const float*)d_in[0];
    const float* pb    = (const float*)d_in[1];
    // d_in[2] = mask: causal, applied analytically
    const float* Wqkv  = (const float*)d_in[3];
    const float* Wout  = (const float*)d_in[4];
    const float* temp  = (const float*)d_in[5];
    const float* Wpre  = (const float*)d_in[6];
    const float* bpre  = (const float*)d_in[7];
    const float* Wpost = (const float*)d_in[8];
    const float* bpost = (const float*)d_in[9];

    float* out  = (float*)d_out;                 // [2048, 1024]
    float* kout = out + NSEQ * CDIM;             // kv[0] = k  [16,2048,64]
    float* vout = kout + HH * NSEQ * DD;         // kv[1] = v

    void *p_qkv, *p_oa;
    cudaGetSymbolAddress(&p_qkv, g_qkv);
    cudaGetSymbolAddress(&p_oa,  g_oa);
    void *p_xhi, *p_xlo, *p_whi, *p_wlo, *p_ohi, *p_olo, *p_ahi, *p_alo;
    cudaGetSymbolAddress(&p_xhi, g_xhi); cudaGetSymbolAddress(&p_xlo, g_xlo);
    cudaGetSymbolAddress(&p_whi, g_whi); cudaGetSymbolAddress(&p_wlo, g_wlo);
    cudaGetSymbolAddress(&p_ohi, g_ohi); cudaGetSymbolAddress(&p_olo, g_olo);
    cudaGetSymbolAddress(&p_ahi, g_ahi); cudaGetSymbolAddress(&p_alo, g_alo);

    // 0. bf16 hi/lo splits of x, W_qkv, W_out
    conv_split<<<(NSEQ * CDIM) / 256, 256>>>(x, (__nv_bfloat16*)p_xhi,
                                             (__nv_bfloat16*)p_xlo, NSEQ * CDIM);
    conv_split<<<(FDIM * CDIM) / 256, 256>>>(Wqkv, (__nv_bfloat16*)p_whi,
                                             (__nv_bfloat16*)p_wlo, FDIM * CDIM);
    conv_split<<<(CDIM * CDIM) / 256, 256>>>(Wout, (__nv_bfloat16*)p_ohi,
                                             (__nv_bfloat16*)p_olo, CDIM * CDIM);

    // 1. qkv = x @ W_qkv^T  (warp-MMA bf16x3)
    hmma_gemm<<<dim3(FDIM / 64, NSEQ / 128), 256>>>(
        (const __nv_bfloat16*)p_xhi, (const __nv_bfloat16*)p_xlo,
        (const __nv_bfloat16*)p_whi, (const __nv_bfloat16*)p_wlo,
        (float*)p_qkv, CDIM, FDIM);

    // 2. split + l2norm + kv outputs
    split_norm<<<dim3(NSEQ, HH), 64>>>(kout, vout);
    // 3. sum_j v  (b_post term)
    sumv_k<<<HH, DD>>>();
    // 4. scores: dots*temp -> pre-mix -> +pos_bias (causal tiles only)
    scores_k<<<dim3(64, 64), 256>>>(Wpre, bpre, pb, temp);
    // 5. row max / sum-exp
    rowstat_k<<<dim3(NSEQ, HH), 256>>>();
    // 6. softmax + post-mix (in place)
    postmix_k<<<dim3(NSEQ / 256, NSEQ), 256>>>(Wpost);
    // 7. attn @ V  (+ b_post * sum v)
    av_k<<<dim3(NSEQ / 64, HH), 256>>>(bpost);

    // 8. out = oa @ W_out^T  (warp-MMA bf16x3)
    conv_split<<<(NSEQ * CDIM) / 256, 256>>>((const float*)p_oa,
                                             (__nv_bfloat16*)p_ahi,
                                             (__nv_bfloat16*)p_alo, NSEQ * CDIM);
    hmma_gemm<<<dim3(CDIM / 64, NSEQ / 128), 256>>>(
        (const __nv_bfloat16*)p_ahi, (const __nv_bfloat16*)p_alo,
        (const __nv_bfloat16*)p_ohi, (const __nv_bfloat16*)p_olo,
        out, CDIM, CDIM);
}

// round 9
// speedup vs baseline: 2.0695x; 1.1127x over previous
#include <cuda_runtime.h>
#include <cuda_bf16.h>
#include <math.h>
#include <cstdint>

#define NSEQ 2048
#define CDIM 1024
#define HH 16
#define DD 64
#define FDIM 3072

typedef __nv_bfloat16 bf16;

// ---------------- scratch (static device allocations; no cudaMalloc) --------
__device__ float g_qkv[NSEQ * FDIM];
__device__ float g_S [67108864];               // 16*2048*2048 fp32 = 256 MB
__device__ float g_m [HH * NSEQ];
__device__ float g_l [HH * NSEQ];
__device__ float g_oa[NSEQ * CDIM];
__device__ float g_sumv[HH * DD];

// bf16 hi/lo operands
__device__ bf16 g_xhi[NSEQ * CDIM],  g_xlo[NSEQ * CDIM];
__device__ bf16 g_whi[FDIM * CDIM],  g_wlo[FDIM * CDIM];
__device__ bf16 g_ohi[CDIM * CDIM],  g_olo[CDIM * CDIM];   // W_out
__device__ bf16 g_ahi[NSEQ * CDIM],  g_alo[NSEQ * CDIM];   // oa
__device__ bf16 g_qhi[HH * NSEQ * DD], g_qlo[HH * NSEQ * DD];
__device__ bf16 g_khi[HH * NSEQ * DD], g_klo[HH * NSEQ * DD];
__device__ bf16 g_vthi[HH * DD * NSEQ], g_vtlo[HH * DD * NSEQ];  // V^T [h][d][n]
__device__ bf16 g_Shi[67108864], g_Slo[67108864];                // attn bf16 256 MB

// ---------------- mma.sync wrapper ------------------------------------------
__device__ __forceinline__ void mma_bf16(float* c, const uint32_t* a,
                                         const uint32_t* b)
{
    asm volatile(
        "mma.sync.aligned.m16n8k16.row.col.f32.bf16.bf16.f32 "
        "{%0,%1,%2,%3}, {%4,%5,%6,%7}, {%8,%9}, {%0,%1,%2,%3};"
        : "+f"(c[0]), "+f"(c[1]), "+f"(c[2]), "+f"(c[3])
        : "r"(a[0]), "r"(a[1]), "r"(a[2]), "r"(a[3]), "r"(b[0]), "r"(b[1]));
}

// ---------------- fp32 -> bf16 hi/lo split ----------------------------------
__global__ __launch_bounds__(256) void conv_split(
    const float* __restrict__ in, bf16* __restrict__ hi,
    bf16* __restrict__ lo, int n)
{
    int i = blockIdx.x * 256 + threadIdx.x;
    if (i >= n) return;
    float x = in[i];
    bf16 h = __float2bfloat16(x);
    hi[i] = h;
    lo[i] = __float2bfloat16(x - __bfloat162float(h));
}

// ---------------- warp-MMA bf16x3 GEMM: C[M,Nn] = A[M,K] * B[Nn,K]^T --------
#define ASTR 24   // padded bf16 row stride (16-wide chunks)

__global__ __launch_bounds__(256) void hmma_gemm(
    const bf16* __restrict__ Ahi, const bf16* __restrict__ Alo,
    const bf16* __restrict__ Bhi, const bf16* __restrict__ Blo,
    float* __restrict__ C, int K, int ldc)
{
    __shared__ __align__(16) bf16 Ah[128 * ASTR], Al[128 * ASTR];
    __shared__ __align__(16) bf16 Bh[64 * ASTR],  Bl[64 * ASTR];

    int tid = threadIdx.x, lane = tid & 31, wid = tid >> 5;
    int wm = wid & 3, wn = wid >> 2;
    int bm = blockIdx.y, bn = blockIdx.x;
    int tq = lane >> 2;
    int tk = (lane & 3) * 2;

    float acc[2][4][4] = {};

    for (int k0 = 0; k0 < K; k0 += 16) {
        #pragma unroll
        for (int l = 0; l < 2; l++) {
            int idx = tid + l * 256;
            int r = idx >> 2, c4 = idx & 3;
            size_t g = (size_t)(bm * 128 + r) * K + k0 + c4 * 4;
            *(uint2*)&Ah[r * ASTR + c4 * 4] = *(const uint2*)(Ahi + g);
            *(uint2*)&Al[r * ASTR + c4 * 4] = *(const uint2*)(Alo + g);
        }
        {
            int r = tid >> 2, c4 = tid & 3;
            size_t g = (size_t)(bn * 64 + r) * K + k0 + c4 * 4;
            *(uint2*)&Bh[r * ASTR + c4 * 4] = *(const uint2*)(Bhi + g);
            *(uint2*)&Bl[r * ASTR + c4 * 4] = *(const uint2*)(Blo + g);
        }
        __syncthreads();

        uint32_t ah[2][4], al[2][4], bh[4][2], bl[4][2];
        #pragma unroll
        for (int t = 0; t < 2; t++) {
            int m = (wm * 32 + t * 16 + tq) * ASTR;
            ah[t][0] = *(const uint32_t*)&Ah[m + tk];
            ah[t][1] = *(const uint32_t*)&Ah[m + 8 * ASTR + tk];
            ah[t][2] = *(const uint32_t*)&Ah[m + tk + 8];
            ah[t][3] = *(const uint32_t*)&Ah[m + 8 * ASTR + tk + 8];
            al[t][0] = *(const uint32_t*)&Al[m + tk];
            al[t][1] = *(const uint32_t*)&Al[m + 8 * ASTR + tk];
            al[t][2] = *(const uint32_t*)&Al[m + tk + 8];
            al[t][3] = *(const uint32_t*)&Al[m + 8 * ASTR + tk + 8];
        }
        #pragma unroll
        for (int n = 0; n < 4; n++) {
            int r = (wn * 32 + n * 8 + tq) * ASTR;
            bh[n][0] = *(const uint32_t*)&Bh[r + tk];
            bh[n][1] = *(const uint32_t*)&Bh[r + tk + 8];
            bl[n][0] = *(const uint32_t*)&Bl[r + tk];
            bl[n][1] = *(const uint32_t*)&Bl[r + tk + 8];
        }
        #pragma unroll
        for (int t = 0; t < 2; t++)
            #pragma unroll
            for (int n = 0; n < 4; n++) {
                mma_bf16(acc[t][n], ah[t], bh[n]);
                mma_bf16(acc[t][n], al[t], bh[n]);
                mma_bf16(acc[t][n], ah[t], bl[n]);
            }
        __syncthreads();
    }

    #pragma unroll
    for (int t = 0; t < 2; t++) {
        int row = bm * 128 + wm * 32 + t * 16 + tq;
        #pragma unroll
        for (int n = 0; n < 4; n++) {
            int col = bn * 64 + wn * 32 + n * 8 + tk;
            *(float2*)&C[(size_t)row * ldc + col] =
                make_float2(acc[t][n][0], acc[t][n][1]);
            *(float2*)&C[(size_t)(row + 8) * ldc + col] =
                make_float2(acc[t][n][2], acc[t][n][3]);
        }
    }
}

// ---------------- split qkv, l2-normalize -> bf16 hi/lo, emit kv ------------
__global__ void split_norm(float* __restrict__ kout, float* __restrict__ vout)
{
    int n = blockIdx.x, h = blockIdx.y, d = threadIdx.x;   // 64 threads
    int base = n * FDIM + (h * DD + d) * 3;
    float q = g_qkv[base + 0];
    float k = g_qkv[base + 1];
    float v = g_qkv[base + 2];

    float sq = q * q, sk = k * k;
    #pragma unroll
    for (int off = 16; off > 0; off >>= 1) {
        sq += __shfl_xor_sync(0xffffffffu, sq, off);
        sk += __shfl_xor_sync(0xffffffffu, sk, off);
    }
    __shared__ float red[4];
    int w = d >> 5, lane = d & 31;
    if (lane == 0) { red[w] = sq; red[2 + w] = sk; }
    __syncthreads();
    float nq = sqrtf(red[0] + red[1]);
    float nk = sqrtf(red[2] + red[3]);

    int o = (h * NSEQ + n) * DD + d;
    float qn = q / fmaxf(nq, 1e-12f);
    float kn = k / fmaxf(nk, 1e-12f);
    bf16 qh = __float2bfloat16(qn);
    bf16 kh = __float2bfloat16(kn);
    g_qhi[o] = qh; g_qlo[o] = __float2bfloat16(qn - __bfloat162float(qh));
    g_khi[o] = kh; g_klo[o] = __float2bfloat16(kn - __bfloat162float(kh));
    kout[o] = k;
    vout[o] = v;
}

// ---------------- V transpose: vout[h][n][d] -> vt[h][d][n] bf16 hi/lo ------
__global__ __launch_bounds__(256) void transpose_v(const float* __restrict__ vout)
{
    int h = blockIdx.z, n0 = blockIdx.x * 32, d0 = blockIdx.y * 32;
    __shared__ float t[32][33];
    int tid = threadIdx.x, tx = tid & 31, ty = tid >> 5;
    #pragma unroll
    for (int r = ty; r < 32; r += 8)
        t[r][tx] = vout[(size_t)(h * NSEQ + n0 + r) * DD + d0 + tx];
    __syncthreads();
    #pragma unroll
    for (int r = ty; r < 32; r += 8) {
        float v = t[tx][r];
        bf16 hv = __float2bfloat16(v);
        size_t o = (size_t)(h * DD + d0 + r) * NSEQ + n0 + tx;
        g_vthi[o] = hv;
        g_vtlo[o] = __float2bfloat16(v - __bfloat162float(hv));
    }
}

// ---------------- sum of V over sequence (for b_post term) -----------------
__global__ void sumv_k(const float* __restrict__ vout)
{
    int g = blockIdx.x, d = threadIdx.x;
    float s = 0.f;
    for (int j = 0; j < NSEQ; j++) s += vout[(size_t)(g * NSEQ + j) * DD + d];
    g_sumv[g * DD + d] = s;
}

// ---------------- HMMA dots: g_S[h][i][j] = temp * qn.kn  (64x64 tiles) -----
#define TSTR 72
__global__ __launch_bounds__(128) void dots_k(const float* __restrict__ temp_p)
{
    int jt = blockIdx.x, it = blockIdx.y, h = blockIdx.z;
    if (jt > it) return;
    __shared__ __align__(16) bf16 Qh[64 * TSTR], Ql[64 * TSTR];
    __shared__ __align__(16) bf16 Kh[64 * TSTR], Kl[64 * TSTR];

    int tid = threadIdx.x, lane = tid & 31, wid = tid >> 5;
    int i0 = it * 64, j0 = jt * 64;
    int tq = lane >> 2, tk = (lane & 3) * 2;

    #pragma unroll
    for (int l = 0; l < 4; l++) {
        int idx = tid + l * 128;
        int r = idx >> 3, c8 = (idx & 7) * 8;
        size_t gq = (size_t)(h * NSEQ + i0 + r) * DD + c8;
        size_t gk = (size_t)(h * NSEQ + j0 + r) * DD + c8;
        *(uint4*)&Qh[r * TSTR + c8] = *(const uint4*)(g_qhi + gq);
        *(uint4*)&Ql[r * TSTR + c8] = *(const uint4*)(g_qlo + gq);
        *(uint4*)&Kh[r * TSTR + c8] = *(const uint4*)(g_khi + gk);
        *(uint4*)&Kl[r * TSTR + c8] = *(const uint4*)(g_klo + gk);
    }
    __syncthreads();

    float acc[8][4] = {};
    int m = wid * 16;
    #pragma unroll
    for (int ki = 0; ki < 4; ki++) {
        int kk = ki * 16 + tk;
        uint32_t ah[4], al[4];
        ah[0] = *(const uint32_t*)&Qh[(m + tq) * TSTR + kk];
        ah[1] = *(const uint32_t*)&Qh[(m + tq + 8) * TSTR + kk];
        ah[2] = *(const uint32_t*)&Qh[(m + tq) * TSTR + kk + 8];
        ah[3] = *(const uint32_t*)&Qh[(m + tq + 8) * TSTR + kk + 8];
        al[0] = *(const uint32_t*)&Ql[(m + tq) * TSTR + kk];
        al[1] = *(const uint32_t*)&Ql[(m + tq + 8) * TSTR + kk];
        al[2] = *(const uint32_t*)&Ql[(m + tq) * TSTR + kk + 8];
        al[3] = *(const uint32_t*)&Ql[(m + tq + 8) * TSTR + kk + 8];
        #pragma unroll
        for (int n = 0; n < 8; n++) {
            uint32_t bh[2], bl[2];
            bh[0] = *(const uint32_t*)&Kh[(n * 8 + tq) * TSTR + kk];
            bh[1] = *(const uint32_t*)&Kh[(n * 8 + tq) * TSTR + kk + 8];
            bl[0] = *(const uint32_t*)&Kl[(n * 8 + tq) * TSTR + kk];
            bl[1] = *(const uint32_t*)&Kl[(n * 8 + tq) * TSTR + kk + 8];
            mma_bf16(acc[n], ah, bh);
            mma_bf16(acc[n], al, bh);
            mma_bf16(acc[n], ah, bl);
        }
    }

    float temp = __ldg(temp_p);
    int row = i0 + m + tq;
    #pragma unroll
    for (int n = 0; n < 8; n++) {
        int col = j0 + n * 8 + tk;
        *(float2*)&g_S[(size_t)(h * NSEQ + row) * NSEQ + col] =
            make_float2(acc[n][0] * temp, acc[n][1] * temp);
        *(float2*)&g_S[(size_t)(h * NSEQ + row + 8) * NSEQ + col] =
            make_float2(acc[n][2] * temp, acc[n][3] * temp);
    }
}

// ---------------- premix (in place) + fused row max/sum-exp -----------------
__global__ __launch_bounds__(256) void premix_rowstat(
    const float* __restrict__ Wpre, const float* __restrict__ bpre,
    const float* __restrict__ pb)
{
    int i = blockIdx.x, tid = threadIdx.x;
    __shared__ float w[256], bp[16];
    __shared__ float pm[16][8], pl[16][8];
    w[tid] = Wpre[tid];
    if (tid < 16) bp[tid] = bpre[tid];
    __syncthreads();

    float mm[16], ll[16];
    #pragma unroll
    for (int g = 0; g < 16; g++) { mm[g] = -INFINITY; ll[g] = 0.f; }

    for (int j = tid; j <= i; j += 256) {
        float d16[16];
        #pragma unroll
        for (int h = 0; h < 16; h++)
            d16[h] = g_S[(size_t)(h * NSEQ + i) * NSEQ + j];
        #pragma unroll
        for (int g = 0; g < 16; g++) {
            float val = bp[g] + pb[(size_t)(g * NSEQ + i) * NSEQ + j];
            #pragma unroll
            for (int h = 0; h < 16; h++)
                val = fmaf(w[g * 16 + h], d16[h], val);
            float nm = fmaxf(mm[g], val);
            ll[g] = ll[g] * __expf(mm[g] - nm) + __expf(val - nm);
            mm[g] = nm;
            g_S[(size_t)(g * NSEQ + i) * NSEQ + j] = val;
        }
    }

    // warp reduce each g
    #pragma unroll
    for (int g = 0; g < 16; g++) {
        #pragma unroll
        for (int off = 16; off > 0; off >>= 1) {
            float mo = __shfl_xor_sync(0xffffffffu, mm[g], off);
            float lo = __shfl_xor_sync(0xffffffffu, ll[g], off);
            float M = fmaxf(mm[g], mo);
            float L = (M == -INFINITY) ? 0.f
                      : ll[g] * __expf(mm[g] - M) + lo * __expf(mo - M);
            mm[g] = M; ll[g] = L;
        }
        if ((tid & 31) == 0) { pm[g][tid >> 5] = mm[g]; pl[g][tid >> 5] = ll[g]; }
    }
    __syncthreads();
    if (tid < 16) {
        float M = -INFINITY, L = 0.f;
        #pragma unroll
        for (int ww = 0; ww < 8; ww++) {
            float m2 = pm[tid][ww], l2 = pl[tid][ww];
            float Mn = fmaxf(M, m2);
            L = (Mn == -INFINITY) ? 0.f
                : L * __expf(M - Mn) + l2 * __expf(m2 - Mn);
            M = Mn;
        }
        g_m[tid * NSEQ + i] = M;
        g_l[tid * NSEQ + i] = L;
    }
}

// ---------------- softmax + post-mix -> attn bf16 hi/lo ---------------------
__global__ __launch_bounds__(256) void postmix_k(const float* __restrict__ Wpost)
{
    __shared__ float w[256];
    int tid = threadIdx.x;
    w[tid] = Wpost[tid];
    int i = blockIdx.y;
    int j = blockIdx.x * 256 + tid;
    __syncthreads();
    if (j > i) return;

    float a[16];
    #pragma unroll
    for (int h = 0; h < 16; h++) {
        float s = g_S[(size_t)(h * NSEQ + i) * NSEQ + j];
        a[h] = __expf(s - g_m[h * NSEQ + i]) / g_l[h * NSEQ + i];
    }
    #pragma unroll
    for (int g = 0; g < 16; g++) {
        float val = 0.f;
        #pragma unroll
        for (int h = 0; h < 16; h++) val = fmaf(w[g * 16 + h], a[h], val);
        size_t idx = (size_t)(g * NSEQ + i) * NSEQ + j;
        bf16 hv = __float2bfloat16(val);
        g_Shi[idx] = hv;
        g_Slo[idx] = __float2bfloat16(val - __bfloat162float(hv));
    }
}

// ---------------- HMMA attn @ V  -> oa[n][(h d)] ----------------------------
__global__ __launch_bounds__(128) void av2_k(const float* __restrict__ bpost)
{
    int it = blockIdx.x, h = blockIdx.y;
    int i0 = it * 64;
    __shared__ __align__(16) bf16 Ah[64 * TSTR], Al[64 * TSTR];
    __shared__ __align__(16) bf16 Bh[64 * TSTR], Bl[64 * TSTR];

    int tid = threadIdx.x, lane = tid & 31, wid = tid >> 5;
    int tq = lane >> 2, tk = (lane & 3) * 2;
    int m = wid * 16;

    float acc[8][4] = {};

    for (int j0 = 0; j0 <= i0; j0 += 64) {
        if (j0 < i0) {
            #pragma unroll
            for (int l = 0; l < 4; l++) {
                int idx = tid + l * 128;
                int r = idx >> 3, c8 = (idx & 7) * 8;
                size_t ga = (size_t)(h * NSEQ + i0 + r) * NSEQ + j0 + c8;
                *(uint4*)&Ah[r * TSTR + c8] = *(const uint4*)(g_Shi + ga);
                *(uint4*)&Al[r * TSTR + c8] = *(const uint4*)(g_Slo + ga);
            }
        } else {
            #pragma unroll 4
            for (int l = 0; l < 32; l++) {
                int idx = tid + l * 128;
                int r = idx >> 6, c = idx & 63;
                bool ok = (j0 + c) <= (i0 + r);
                size_t ga = (size_t)(h * NSEQ + i0 + r) * NSEQ + j0 + c;
                Ah[r * TSTR + c] = ok ? g_Shi[ga] : (bf16)__float2bfloat16(0.f);
                Al[r * TSTR + c] = ok ? g_Slo[ga] : (bf16)__float2bfloat16(0.f);
            }
        }
        #pragma unroll
        for (int l = 0; l < 4; l++) {
            int idx = tid + l * 128;
            int r = idx >> 3, c8 = (idx & 7) * 8;
            size_t gb = (size_t)(h * DD + r) * NSEQ + j0 + c8;
            *(uint4*)&Bh[r * TSTR + c8] = *(const uint4*)(g_vthi + gb);
            *(uint4*)&Bl[r * TSTR + c8] = *(const uint4*)(g_vtlo + gb);
        }
        __syncthreads();

        #pragma unroll
        for (int ki = 0; ki < 4; ki++) {
            int kk = ki * 16 + tk;
            uint32_t ah[4], al[4];
            ah[0] = *(const uint32_t*)&Ah[(m + tq) * TSTR + kk];
            ah[1] = *(const uint32_t*)&Ah[(m + tq + 8) * TSTR + kk];
            ah[2] = *(const uint32_t*)&Ah[(m + tq) * TSTR + kk + 8];
            ah[3] = *(const uint32_t*)&Ah[(m + tq + 8) * TSTR + kk + 8];
            al[0] = *(const uint32_t*)&Al[(m + tq) * TSTR + kk];
            al[1] = *(const uint32_t*)&Al[(m + tq + 8) * TSTR + kk];
            al[2] = *(const uint32_t*)&Al[(m + tq) * TSTR + kk + 8];
            al[3] = *(const uint32_t*)&Al[(m + tq + 8) * TSTR + kk + 8];
            #pragma unroll
            for (int n = 0; n < 8; n++) {
                uint32_t bh[2], bl[2];
                bh[0] = *(const uint32_t*)&Bh[(n * 8 + tq) * TSTR + kk];
                bh[1] = *(const uint32_t*)&Bh[(n * 8 + tq) * TSTR + kk + 8];
                bl[0] = *(const uint32_t*)&Bl[(n * 8 + tq) * TSTR + kk];
                bl[1] = *(const uint32_t*)&Bl[(n * 8 + tq) * TSTR + kk + 8];
                mma_bf16(acc[n], ah, bh);
                mma_bf16(acc[n], al, bh);
                mma_bf16(acc[n], ah, bl);
            }
        }
        __syncthreads();
    }

    float bpv = bpost[h];
    int row = i0 + m + tq;
    #pragma unroll
    for (int n = 0; n < 8; n++) {
        int d = n * 8 + tk;
        float s0 = bpv * g_sumv[h * DD + d];
        float s1 = bpv * g_sumv[h * DD + d + 1];
        *(float2*)&g_oa[(size_t)row * CDIM + h * DD + d] =
            make_float2(acc[n][0] + s0, acc[n][1] + s1);
        *(float2*)&g_oa[(size_t)(row + 8) * CDIM + h * DD + d] =
            make_float2(acc[n][2] + s0, acc[n][3] + s1);
    }
}

// ---------------- launch -----------------------------------------------------
extern "C" void kernel_launch(void* const* d_in, const int* in_sizes, int n_in,
                              void* d_out, int out_size)
{
    const float* x     = (const float*)d_in[0];
    const float* pb    = (const float*)d_in[1];
    // d_in[2] = mask: causal, applied analytically
    const float* Wqkv  = (const float*)d_in[3];
    const float* Wout  = (const float*)d_in[4];
    const float* temp  = (const float*)d_in[5];
    const float* Wpre  = (const float*)d_in[6];
    const float* bpre  = (const float*)d_in[7];
    const float* Wpost = (const float*)d_in[8];
    const float* bpost = (const float*)d_in[9];

    float* out  = (float*)d_out;                 // [2048, 1024]
    float* kout = out + NSEQ * CDIM;             // kv[0] = k  [16,2048,64]
    float* vout = kout + HH * NSEQ * DD;         // kv[1] = v

    void *p_qkv, *p_oa;
    cudaGetSymbolAddress(&p_qkv, g_qkv);
    cudaGetSymbolAddress(&p_oa,  g_oa);
    void *p_xhi, *p_xlo, *p_whi, *p_wlo, *p_ohi, *p_olo, *p_ahi, *p_alo;
    cudaGetSymbolAddress(&p_xhi, g_xhi); cudaGetSymbolAddress(&p_xlo, g_xlo);
    cudaGetSymbolAddress(&p_whi, g_whi); cudaGetSymbolAddress(&p_wlo, g_wlo);
    cudaGetSymbolAddress(&p_ohi, g_ohi); cudaGetSymbolAddress(&p_olo, g_olo);
    cudaGetSymbolAddress(&p_ahi, g_ahi); cudaGetSymbolAddress(&p_alo, g_alo);

    // 0. bf16 hi/lo splits of x, W_qkv, W_out
    conv_split<<<(NSEQ * CDIM) / 256, 256>>>(x, (bf16*)p_xhi, (bf16*)p_xlo,
                                             NSEQ * CDIM);
    conv_split<<<(FDIM * CDIM) / 256, 256>>>(Wqkv, (bf16*)p_whi, (bf16*)p_wlo,
                                             FDIM * CDIM);
    conv_split<<<(CDIM * CDIM) / 256, 256>>>(Wout, (bf16*)p_ohi, (bf16*)p_olo,
                                             CDIM * CDIM);

    // 1. qkv = x @ W_qkv^T  (HMMA bf16x3)
    hmma_gemm<<<dim3(FDIM / 64, NSEQ / 128), 256>>>(
        (const bf16*)p_xhi, (const bf16*)p_xlo,
        (const bf16*)p_whi, (const bf16*)p_wlo, (float*)p_qkv, CDIM, FDIM);

    // 2. split + l2norm -> bf16 hi/lo; kv outputs
    split_norm<<<dim3(NSEQ, HH), 64>>>(kout, vout);
    // 3. V transpose -> bf16 hi/lo [h][d][n]; sum_j v
    transpose_v<<<dim3(NSEQ / 32, DD / 32, HH), 256>>>(vout);
    sumv_k<<<HH, DD>>>(vout);
    // 4. raw dots (HMMA)
    dots_k<<<dim3(32, 32, HH), 128>>>(temp);
    // 5. premix + pos_bias + row stats (fused, in place)
    premix_rowstat<<<NSEQ, 256>>>(Wpre, bpre, pb);
    // 6. softmax + post-mix -> attn bf16 hi/lo
    postmix_k<<<dim3(NSEQ / 256, NSEQ), 256>>>(Wpost);
    // 7. attn @ V (HMMA) + b_post * sum v
    av2_k<<<dim3(NSEQ / 64, HH), 128>>>(bpost);

    // 8. out = oa @ W_out^T  (HMMA bf16x3)
    conv_split<<<(NSEQ * CDIM) / 256, 256>>>((const float*)p_oa,
                                             (bf16*)p_ahi, (bf16*)p_alo,
                                             NSEQ * CDIM);
    hmma_gemm<<<dim3(CDIM / 64, NSEQ / 128), 256>>>(
        (const bf16*)p_ahi, (const bf16*)p_alo,
        (const bf16*)p_ohi, (const bf16*)p_olo, out, CDIM, CDIM);
}

// round 12
// speedup vs baseline: 2.3294x; 1.1256x over previous
#include <cuda_runtime.h>
#include <cuda_bf16.h>
#include <math.h>
#include <cstdint>

#define NSEQ 2048
#define CDIM 1024
#define HH 16
#define DD 64
#define FDIM 3072

typedef __nv_bfloat16 bf16;

// ---------------- scratch (static device allocations; no cudaMalloc) --------
__device__ float g_qkv[NSEQ * FDIM];
__device__ float g_S [67108864];               // 16*2048*2048 fp32 = 256 MB
__device__ float g_m [HH * NSEQ];
__device__ float g_l [HH * NSEQ];
__device__ float g_sumv[HH * DD];

// bf16 hi/lo operands
__device__ bf16 g_xhi[NSEQ * CDIM],  g_xlo[NSEQ * CDIM];
__device__ bf16 g_whi[FDIM * CDIM],  g_wlo[FDIM * CDIM];
__device__ bf16 g_ohi[CDIM * CDIM],  g_olo[CDIM * CDIM];   // W_out
__device__ bf16 g_ahi[NSEQ * CDIM],  g_alo[NSEQ * CDIM];   // attn@V output
__device__ bf16 g_qhi[HH * NSEQ * DD], g_qlo[HH * NSEQ * DD];
__device__ bf16 g_khi[HH * NSEQ * DD], g_klo[HH * NSEQ * DD];
__device__ bf16 g_vthi[HH * DD * NSEQ], g_vtlo[HH * DD * NSEQ];  // V^T [h][d][n]
__device__ bf16 g_Shi[67108864], g_Slo[67108864];                // attn bf16

// ---------------- helpers ----------------------------------------------------
__device__ __forceinline__ uint32_t smem_u32(const void* p) {
    uint32_t a;
    asm("{ .reg .u64 t; cvta.to.shared.u64 t, %1; cvt.u32.u64 %0, t; }"
        : "=r"(a) : "l"(p));
    return a;
}
__device__ __forceinline__ void cp16(uint32_t saddr, const void* gptr) {
    asm volatile("cp.async.ca.shared.global [%0], [%1], 16;"
                 :: "r"(saddr), "l"(gptr) : "memory");
}
__device__ __forceinline__ void mma_bf16(float* c, const uint32_t* a,
                                         const uint32_t* b)
{
    asm volatile(
        "mma.sync.aligned.m16n8k16.row.col.f32.bf16.bf16.f32 "
        "{%0,%1,%2,%3}, {%4,%5,%6,%7}, {%8,%9}, {%0,%1,%2,%3};"
        : "+f"(c[0]), "+f"(c[1]), "+f"(c[2]), "+f"(c[3])
        : "r"(a[0]), "r"(a[1]), "r"(a[2]), "r"(a[3]), "r"(b[0]), "r"(b[1]));
}

// ---------------- fp32 -> bf16 hi/lo split ----------------------------------
__global__ __launch_bounds__(256) void conv_split(
    const float* __restrict__ in, bf16* __restrict__ hi,
    bf16* __restrict__ lo, int n)
{
    int i = blockIdx.x * 256 + threadIdx.x;
    if (i >= n) return;
    float x = in[i];
    bf16 h = __float2bfloat16(x);
    hi[i] = h;
    lo[i] = __float2bfloat16(x - __bfloat162float(h));
}

// ---------------- pipelined warp-MMA bf16x3 GEMM ----------------------------
// C[M,Nn] = A[M,K] * B[Nn,K]^T.  Tile 128x64, BK=32, 2-stage cp.async.
#define STR2 40                               // padded bf16 row stride
#define A_BYTES (128 * STR2 * 2)              // 10240 per split
#define B_BYTES (64  * STR2 * 2)              // 5120  per split
#define STAGE_BYTES (2 * A_BYTES + 2 * B_BYTES)   // 30720
#define GEMM_SMEM (2 * STAGE_BYTES)               // 61440

#define ISSUE_STAGE(stg, k0) do {                                          \
    uint32_t s_ = sbase + (stg) * STAGE_BYTES;                             \
    _Pragma("unroll")                                                      \
    for (int l_ = 0; l_ < 2; l_++) {                                       \
        int idx_ = tid + l_ * 256;                                         \
        int r_ = idx_ >> 2, c_ = idx_ & 3;                                 \
        uint32_t so_ = s_ + r_ * 80 + c_ * 16;                             \
        size_t g_ = (size_t)(bm * 128 + r_) * K + (k0) + c_ * 8;           \
        cp16(so_,           Ahi + g_);                                     \
        cp16(so_ + A_BYTES, Alo + g_);                                     \
    }                                                                      \
    {                                                                      \
        int r_ = tid >> 2, c_ = tid & 3;                                   \
        uint32_t so_ = s_ + 2 * A_BYTES + r_ * 80 + c_ * 16;               \
        size_t g_ = (size_t)(bn * 64 + r_) * K + (k0) + c_ * 8;            \
        cp16(so_,           Bhi + g_);                                     \
        cp16(so_ + B_BYTES, Blo + g_);                                     \
    }                                                                      \
    asm volatile("cp.async.commit_group;" ::: "memory");                   \
} while (0)

__global__ __launch_bounds__(256) void hmma_gemm(
    const bf16* __restrict__ Ahi, const bf16* __restrict__ Alo,
    const bf16* __restrict__ Bhi, const bf16* __restrict__ Blo,
    float* __restrict__ C, int K, int ldc)
{
    extern __shared__ __align__(16) char sm[];
    uint32_t sbase = smem_u32(sm);

    int tid = threadIdx.x, lane = tid & 31, wid = tid >> 5;
    int wm = wid & 3, wn = wid >> 2;
    int bm = blockIdx.y, bn = blockIdx.x;
    int tq = lane >> 2, tk = (lane & 3) * 2;

    float acc[2][4][4] = {};

    ISSUE_STAGE(0, 0);
    int nch = K >> 5;
    for (int ch = 0; ch < nch; ch++) {
        if (ch + 1 < nch) {
            ISSUE_STAGE((ch + 1) & 1, (ch + 1) << 5);
            asm volatile("cp.async.wait_group 1;" ::: "memory");
        } else {
            asm volatile("cp.async.wait_group 0;" ::: "memory");
        }
        __syncthreads();

        const bf16* Ah = (const bf16*)(sm + (ch & 1) * STAGE_BYTES);
        const bf16* Al = Ah + 128 * STR2;
        const bf16* Bh = Al + 128 * STR2;
        const bf16* Bl = Bh + 64 * STR2;

        #pragma unroll
        for (int ks = 0; ks < 2; ks++) {
            int kc = ks * 16 + tk;
            uint32_t ah[2][4], al[2][4], bh[4][2], bl[4][2];
            #pragma unroll
            for (int t = 0; t < 2; t++) {
                int m = (wm * 32 + t * 16 + tq) * STR2;
                ah[t][0] = *(const uint32_t*)&Ah[m + kc];
                ah[t][1] = *(const uint32_t*)&Ah[m + 8 * STR2 + kc];
                ah[t][2] = *(const uint32_t*)&Ah[m + kc + 8];
                ah[t][3] = *(const uint32_t*)&Ah[m + 8 * STR2 + kc + 8];
                al[t][0] = *(const uint32_t*)&Al[m + kc];
                al[t][1] = *(const uint32_t*)&Al[m + 8 * STR2 + kc];
                al[t][2] = *(const uint32_t*)&Al[m + kc + 8];
                al[t][3] = *(const uint32_t*)&Al[m + 8 * STR2 + kc + 8];
            }
            #pragma unroll
            for (int n = 0; n < 4; n++) {
                int r = (wn * 32 + n * 8 + tq) * STR2;
                bh[n][0] = *(const uint32_t*)&Bh[r + kc];
                bh[n][1] = *(const uint32_t*)&Bh[r + kc + 8];
                bl[n][0] = *(const uint32_t*)&Bl[r + kc];
                bl[n][1] = *(const uint32_t*)&Bl[r + kc + 8];
            }
            #pragma unroll
            for (int t = 0; t < 2; t++)
                #pragma unroll
                for (int n = 0; n < 4; n++) {
                    mma_bf16(acc[t][n], ah[t], bh[n]);
                    mma_bf16(acc[t][n], al[t], bh[n]);
                    mma_bf16(acc[t][n], ah[t], bl[n]);
                }
        }
        __syncthreads();
    }

    #pragma unroll
    for (int t = 0; t < 2; t++) {
        int row = bm * 128 + wm * 32 + t * 16 + tq;
        #pragma unroll
        for (int n = 0; n < 4; n++) {
            int col = bn * 64 + wn * 32 + n * 8 + tk;
            *(float2*)&C[(size_t)row * ldc + col] =
                make_float2(acc[t][n][0], acc[t][n][1]);
            *(float2*)&C[(size_t)(row + 8) * ldc + col] =
                make_float2(acc[t][n][2], acc[t][n][3]);
        }
    }
}

// ---------------- split qkv, l2-normalize -> bf16 hi/lo, emit kv ------------
__global__ void split_norm(float* __restrict__ kout, float* __restrict__ vout)
{
    int n = blockIdx.x, h = blockIdx.y, d = threadIdx.x;   // 64 threads
    int base = n * FDIM + (h * DD + d) * 3;
    float q = g_qkv[base + 0];
    float k = g_qkv[base + 1];
    float v = g_qkv[base + 2];

    float sq = q * q, sk = k * k;
    #pragma unroll
    for (int off = 16; off > 0; off >>= 1) {
        sq += __shfl_xor_sync(0xffffffffu, sq, off);
        sk += __shfl_xor_sync(0xffffffffu, sk, off);
    }
    __shared__ float red[4];
    int w = d >> 5, lane = d & 31;
    if (lane == 0) { red[w] = sq; red[2 + w] = sk; }
    __syncthreads();
    float nq = sqrtf(red[0] + red[1]);
    float nk = sqrtf(red[2] + red[3]);

    int o = (h * NSEQ + n) * DD + d;
    float qn = q / fmaxf(nq, 1e-12f);
    float kn = k / fmaxf(nk, 1e-12f);
    bf16 qh = __float2bfloat16(qn);
    bf16 kh = __float2bfloat16(kn);
    g_qhi[o] = qh; g_qlo[o] = __float2bfloat16(qn - __bfloat162float(qh));
    g_khi[o] = kh; g_klo[o] = __float2bfloat16(kn - __bfloat162float(kh));
    kout[o] = k;
    vout[o] = v;
}

// ---------------- V transpose: vout[h][n][d] -> vt[h][d][n] bf16 hi/lo ------
__global__ __launch_bounds__(256) void transpose_v(const float* __restrict__ vout)
{
    int h = blockIdx.z, n0 = blockIdx.x * 32, d0 = blockIdx.y * 32;
    __shared__ float t[32][33];
    int tid = threadIdx.x, tx = tid & 31, ty = tid >> 5;
    #pragma unroll
    for (int r = ty; r < 32; r += 8)
        t[r][tx] = vout[(size_t)(h * NSEQ + n0 + r) * DD + d0 + tx];
    __syncthreads();
    #pragma unroll
    for (int r = ty; r < 32; r += 8) {
        float v = t[tx][r];
        bf16 hv = __float2bfloat16(v);
        size_t o = (size_t)(h * DD + d0 + r) * NSEQ + n0 + tx;
        g_vthi[o] = hv;
        g_vtlo[o] = __float2bfloat16(v - __bfloat162float(hv));
    }
}

// ---------------- sum of V over sequence (for b_post term) -----------------
__global__ __launch_bounds__(256) void sumv_k(const float* __restrict__ vout)
{
    int h = blockIdx.x, tid = threadIdx.x;
    int d = tid & 63, seg = tid >> 6;          // 4 segments
    float s = 0.f;
    for (int j = seg; j < NSEQ; j += 4)
        s += vout[(size_t)(h * NSEQ + j) * DD + d];
    __shared__ float red[256];
    red[tid] = s;
    __syncthreads();
    if (tid < 128) red[tid] += red[tid + 128];
    __syncthreads();
    if (tid < 64) g_sumv[h * DD + tid] = red[tid] + red[tid + 64];
}

// ---------------- HMMA dots: g_S[h][i][j] = temp * qn.kn  (64x64 tiles) -----
#define TSTR 72
__global__ __launch_bounds__(128) void dots_k(const float* __restrict__ temp_p)
{
    int jt = blockIdx.x, it = blockIdx.y, h = blockIdx.z;
    if (jt > it) return;
    __shared__ __align__(16) bf16 Qh[64 * TSTR], Ql[64 * TSTR];
    __shared__ __align__(16) bf16 Kh[64 * TSTR], Kl[64 * TSTR];

    int tid = threadIdx.x, lane = tid & 31, wid = tid >> 5;
    int i0 = it * 64, j0 = jt * 64;
    int tq = lane >> 2, tk = (lane & 3) * 2;

    #pragma unroll
    for (int l = 0; l < 4; l++) {
        int idx = tid + l * 128;
        int r = idx >> 3, c8 = (idx & 7) * 8;
        size_t gq = (size_t)(h * NSEQ + i0 + r) * DD + c8;
        size_t gk = (size_t)(h * NSEQ + j0 + r) * DD + c8;
        *(uint4*)&Qh[r * TSTR + c8] = *(const uint4*)(g_qhi + gq);
        *(uint4*)&Ql[r * TSTR + c8] = *(const uint4*)(g_qlo + gq);
        *(uint4*)&Kh[r * TSTR + c8] = *(const uint4*)(g_khi + gk);
        *(uint4*)&Kl[r * TSTR + c8] = *(const uint4*)(g_klo + gk);
    }
    __syncthreads();

    float acc[8][4] = {};
    int m = wid * 16;
    #pragma unroll
    for (int ki = 0; ki < 4; ki++) {
        int kk = ki * 16 + tk;
        uint32_t ah[4], al[4];
        ah[0] = *(const uint32_t*)&Qh[(m + tq) * TSTR + kk];
        ah[1] = *(const uint32_t*)&Qh[(m + tq + 8) * TSTR + kk];
        ah[2] = *(const uint32_t*)&Qh[(m + tq) * TSTR + kk + 8];
        ah[3] = *(const uint32_t*)&Qh[(m + tq + 8) * TSTR + kk + 8];
        al[0] = *(const uint32_t*)&Ql[(m + tq) * TSTR + kk];
        al[1] = *(const uint32_t*)&Ql[(m + tq + 8) * TSTR + kk];
        al[2] = *(const uint32_t*)&Ql[(m + tq) * TSTR + kk + 8];
        al[3] = *(const uint32_t*)&Ql[(m + tq + 8) * TSTR + kk + 8];
        #pragma unroll
        for (int n = 0; n < 8; n++) {
            uint32_t bh[2], bl[2];
            bh[0] = *(const uint32_t*)&Kh[(n * 8 + tq) * TSTR + kk];
            bh[1] = *(const uint32_t*)&Kh[(n * 8 + tq) * TSTR + kk + 8];
            bl[0] = *(const uint32_t*)&Kl[(n * 8 + tq) * TSTR + kk];
            bl[1] = *(const uint32_t*)&Kl[(n * 8 + tq) * TSTR + kk + 8];
            mma_bf16(acc[n], ah, bh);
            mma_bf16(acc[n], al, bh);
            mma_bf16(acc[n], ah, bl);
        }
    }

    float temp = __ldg(temp_p);
    int row = i0 + m + tq;
    #pragma unroll
    for (int n = 0; n < 8; n++) {
        int col = j0 + n * 8 + tk;
        *(float2*)&g_S[(size_t)(h * NSEQ + row) * NSEQ + col] =
            make_float2(acc[n][0] * temp, acc[n][1] * temp);
        *(float2*)&g_S[(size_t)(h * NSEQ + row + 8) * NSEQ + col] =
            make_float2(acc[n][2] * temp, acc[n][3] * temp);
    }
}

// ---------------- premix (in place) + fused row max/sum-exp -----------------
__global__ __launch_bounds__(256) void premix_rowstat(
    const float* __restrict__ Wpre, const float* __restrict__ bpre,
    const float* __restrict__ pb)
{
    int i = blockIdx.x, tid = threadIdx.x;
    __shared__ float w[256], bp[16];
    __shared__ float pm[16][8], pl[16][8];
    w[tid] = Wpre[tid];
    if (tid < 16) bp[tid] = bpre[tid];
    __syncthreads();

    float mm[16], ll[16];
    #pragma unroll
    for (int g = 0; g < 16; g++) { mm[g] = -INFINITY; ll[g] = 0.f; }

    for (int j = tid; j <= i; j += 256) {
        float d16[16];
        #pragma unroll
        for (int h = 0; h < 16; h++)
            d16[h] = g_S[(size_t)(h * NSEQ + i) * NSEQ + j];
        #pragma unroll
        for (int g = 0; g < 16; g++) {
            float val = bp[g] + pb[(size_t)(g * NSEQ + i) * NSEQ + j];
            #pragma unroll
            for (int h = 0; h < 16; h++)
                val = fmaf(w[g * 16 + h], d16[h], val);
            float nm = fmaxf(mm[g], val);
            ll[g] = ll[g] * __expf(mm[g] - nm) + __expf(val - nm);
            mm[g] = nm;
            g_S[(size_t)(g * NSEQ + i) * NSEQ + j] = val;
        }
    }

    #pragma unroll
    for (int g = 0; g < 16; g++) {
        #pragma unroll
        for (int off = 16; off > 0; off >>= 1) {
            float mo = __shfl_xor_sync(0xffffffffu, mm[g], off);
            float lo = __shfl_xor_sync(0xffffffffu, ll[g], off);
            float M = fmaxf(mm[g], mo);
            float L = (M == -INFINITY) ? 0.f
                      : ll[g] * __expf(mm[g] - M) + lo * __expf(mo - M);
            mm[g] = M; ll[g] = L;
        }
        if ((tid & 31) == 0) { pm[g][tid >> 5] = mm[g]; pl[g][tid >> 5] = ll[g]; }
    }
    __syncthreads();
    if (tid < 16) {
        float M = -INFINITY, L = 0.f;
        #pragma unroll
        for (int ww = 0; ww < 8; ww++) {
            float m2 = pm[tid][ww], l2 = pl[tid][ww];
            float Mn = fmaxf(M, m2);
            L = (Mn == -INFINITY) ? 0.f
                : L * __expf(M - Mn) + l2 * __expf(m2 - Mn);
            M = Mn;
        }
        g_m[tid * NSEQ + i] = M;
        g_l[tid * NSEQ + i] = L;
    }
}

// ---------------- softmax + post-mix -> attn bf16 hi/lo ---------------------
__global__ __launch_bounds__(256) void postmix_k(const float* __restrict__ Wpost)
{
    __shared__ float w[256];
    int tid = threadIdx.x;
    w[tid] = Wpost[tid];
    int i = blockIdx.y;
    int j = blockIdx.x * 256 + tid;
    __syncthreads();
    if (j > i) return;

    float a[16];
    #pragma unroll
    for (int h = 0; h < 16; h++) {
        float s = g_S[(size_t)(h * NSEQ + i) * NSEQ + j];
        a[h] = __expf(s - g_m[h * NSEQ + i]) / g_l[h * NSEQ + i];
    }
    #pragma unroll
    for (int g = 0; g < 16; g++) {
        float val = 0.f;
        #pragma unroll
        for (int h = 0; h < 16; h++) val = fmaf(w[g * 16 + h], a[h], val);
        size_t idx = (size_t)(g * NSEQ + i) * NSEQ + j;
        bf16 hv = __float2bfloat16(val);
        g_Shi[idx] = hv;
        g_Slo[idx] = __float2bfloat16(val - __bfloat162float(hv));
    }
}

// ---------------- HMMA attn @ V  -> bf16 hi/lo [n][(h d)] -------------------
__global__ __launch_bounds__(128) void av2_k(const float* __restrict__ bpost)
{
    int it = blockIdx.x, h = blockIdx.y;
    int i0 = it * 64;
    __shared__ __align__(16) bf16 Ah[64 * TSTR], Al[64 * TSTR];
    __shared__ __align__(16) bf16 Bh[64 * TSTR], Bl[64 * TSTR];

    int tid = threadIdx.x, lane = tid & 31, wid = tid >> 5;
    int tq = lane >> 2, tk = (lane & 3) * 2;
    int m = wid * 16;

    float acc[8][4] = {};

    for (int j0 = 0; j0 <= i0; j0 += 64) {
        if (j0 < i0) {
            #pragma unroll
            for (int l = 0; l < 4; l++) {
                int idx = tid + l * 128;
                int r = idx >> 3, c8 = (idx & 7) * 8;
                size_t ga = (size_t)(h * NSEQ + i0 + r) * NSEQ + j0 + c8;
                *(uint4*)&Ah[r * TSTR + c8] = *(const uint4*)(g_Shi + ga);
                *(uint4*)&Al[r * TSTR + c8] = *(const uint4*)(g_Slo + ga);
            }
        } else {
            #pragma unroll 4
            for (int l = 0; l < 32; l++) {
                int idx = tid + l * 128;
                int r = idx >> 6, c = idx & 63;
                bool ok = (j0 + c) <= (i0 + r);
                size_t ga = (size_t)(h * NSEQ + i0 + r) * NSEQ + j0 + c;
                Ah[r * TSTR + c] = ok ? g_Shi[ga] : (bf16)__float2bfloat16(0.f);
                Al[r * TSTR + c] = ok ? g_Slo[ga] : (bf16)__float2bfloat16(0.f);
            }
        }
        #pragma unroll
        for (int l = 0; l < 4; l++) {
            int idx = tid + l * 128;
            int r = idx >> 3, c8 = (idx & 7) * 8;
            size_t gb = (size_t)(h * DD + r) * NSEQ + j0 + c8;
            *(uint4*)&Bh[r * TSTR + c8] = *(const uint4*)(g_vthi + gb);
            *(uint4*)&Bl[r * TSTR + c8] = *(const uint4*)(g_vtlo + gb);
        }
        __syncthreads();

        #pragma unroll
        for (int ki = 0; ki < 4; ki++) {
            int kk = ki * 16 + tk;
            uint32_t ah[4], al[4];
            ah[0] = *(const uint32_t*)&Ah[(m + tq) * TSTR + kk];
            ah[1] = *(const uint32_t*)&Ah[(m + tq + 8) * TSTR + kk];
            ah[2] = *(const uint32_t*)&Ah[(m + tq) * TSTR + kk + 8];
            ah[3] = *(const uint32_t*)&Ah[(m + tq + 8) * TSTR + kk + 8];
            al[0] = *(const uint32_t*)&Al[(m + tq) * TSTR + kk];
            al[1] = *(const uint32_t*)&Al[(m + tq + 8) * TSTR + kk];
            al[2] = *(const uint32_t*)&Al[(m + tq) * TSTR + kk + 8];
            al[3] = *(const uint32_t*)&Al[(m + tq + 8) * TSTR + kk + 8];
            #pragma unroll
            for (int n = 0; n < 8; n++) {
                uint32_t bh[2], bl[2];
                bh[0] = *(const uint32_t*)&Bh[(n * 8 + tq) * TSTR + kk];
                bh[1] = *(const uint32_t*)&Bh[(n * 8 + tq) * TSTR + kk + 8];
                bl[0] = *(const uint32_t*)&Bl[(n * 8 + tq) * TSTR + kk];
                bl[1] = *(const uint32_t*)&Bl[(n * 8 + tq) * TSTR + kk + 8];
                mma_bf16(acc[n], ah, bh);
                mma_bf16(acc[n], al, bh);
                mma_bf16(acc[n], ah, bl);
            }
        }
        __syncthreads();
    }

    // epilogue: + b_post * sumv, write bf16 hi/lo directly (feeds out-proj)
    float bpv = bpost[h];
    int row = i0 + m + tq;
    #pragma unroll
    for (int n = 0; n < 8; n++) {
        int d = n * 8 + tk;
        float s0 = bpv * g_sumv[h * DD + d];
        float s1 = bpv * g_sumv[h * DD + d + 1];
        float v00 = acc[n][0] + s0, v01 = acc[n][1] + s1;
        float v10 = acc[n][2] + s0, v11 = acc[n][3] + s1;
        size_t o0 = (size_t)row * CDIM + h * DD + d;
        size_t o1 = (size_t)(row + 8) * CDIM + h * DD + d;
        __nv_bfloat162 hi0, hi1, lo0, lo1;
        hi0.x = __float2bfloat16(v00); hi0.y = __float2bfloat16(v01);
        hi1.x = __float2bfloat16(v10); hi1.y = __float2bfloat16(v11);
        lo0.x = __float2bfloat16(v00 - __bfloat162float(hi0.x));
        lo0.y = __float2bfloat16(v01 - __bfloat162float(hi0.y));
        lo1.x = __float2bfloat16(v10 - __bfloat162float(hi1.x));
        lo1.y = __float2bfloat16(v11 - __bfloat162float(hi1.y));
        *(__nv_bfloat162*)&g_ahi[o0] = hi0;
        *(__nv_bfloat162*)&g_ahi[o1] = hi1;
        *(__nv_bfloat162*)&g_alo[o0] = lo0;
        *(__nv_bfloat162*)&g_alo[o1] = lo1;
    }
}

// ---------------- launch -----------------------------------------------------
extern "C" void kernel_launch(void* const* d_in, const int* in_sizes, int n_in,
                              void* d_out, int out_size)
{
    const float* x     = (const float*)d_in[0];
    const float* pb    = (const float*)d_in[1];
    // d_in[2] = mask: causal, applied analytically
    const float* Wqkv  = (const float*)d_in[3];
    const float* Wout  = (const float*)d_in[4];
    const float* temp  = (const float*)d_in[5];
    const float* Wpre  = (const float*)d_in[6];
    const float* bpre  = (const float*)d_in[7];
    const float* Wpost = (const float*)d_in[8];
    const float* bpost = (const float*)d_in[9];

    float* out  = (float*)d_out;                 // [2048, 1024]
    float* kout = out + NSEQ * CDIM;             // kv[0] = k  [16,2048,64]
    float* vout = kout + HH * NSEQ * DD;         // kv[1] = v

    cudaFuncSetAttribute(hmma_gemm,
        cudaFuncAttributeMaxDynamicSharedMemorySize, GEMM_SMEM);

    void* p_qkv;
    cudaGetSymbolAddress(&p_qkv, g_qkv);
    void *p_xhi, *p_xlo, *p_whi, *p_wlo, *p_ohi, *p_olo, *p_ahi, *p_alo;
    cudaGetSymbolAddress(&p_xhi, g_xhi); cudaGetSymbolAddress(&p_xlo, g_xlo);
    cudaGetSymbolAddress(&p_whi, g_whi); cudaGetSymbolAddress(&p_wlo, g_wlo);
    cudaGetSymbolAddress(&p_ohi, g_ohi); cudaGetSymbolAddress(&p_olo, g_olo);
    cudaGetSymbolAddress(&p_ahi, g_ahi); cudaGetSymbolAddress(&p_alo, g_alo);

    // 0. bf16 hi/lo splits of x, W_qkv, W_out
    conv_split<<<(NSEQ * CDIM) / 256, 256>>>(x, (bf16*)p_xhi, (bf16*)p_xlo,
                                             NSEQ * CDIM);
    conv_split<<<(FDIM * CDIM) / 256, 256>>>(Wqkv, (bf16*)p_whi, (bf16*)p_wlo,
                                             FDIM * CDIM);
    conv_split<<<(CDIM * CDIM) / 256, 256>>>(Wout, (bf16*)p_ohi, (bf16*)p_olo,
                                             CDIM * CDIM);

    // 1. qkv = x @ W_qkv^T  (pipelined HMMA bf16x3)
    hmma_gemm<<<dim3(FDIM / 64, NSEQ / 128), 256, GEMM_SMEM>>>(
        (const bf16*)p_xhi, (const bf16*)p_xlo,
        (const bf16*)p_whi, (const bf16*)p_wlo, (float*)p_qkv, CDIM, FDIM);

    // 2. split + l2norm -> bf16 hi/lo; kv outputs
    split_norm<<<dim3(NSEQ, HH), 64>>>(kout, vout);
    // 3. V transpose -> bf16 hi/lo [h][d][n]; sum_j v
    transpose_v<<<dim3(NSEQ / 32, DD / 32, HH), 256>>>(vout);
    sumv_k<<<HH, 256>>>(vout);
    // 4. raw dots (HMMA)
    dots_k<<<dim3(32, 32, HH), 128>>>(temp);
    // 5. premix + pos_bias + row stats (fused, in place)
    premix_rowstat<<<NSEQ, 256>>>(Wpre, bpre, pb);
    // 6. softmax + post-mix -> attn bf16 hi/lo
    postmix_k<<<dim3(NSEQ / 256, NSEQ), 256>>>(Wpost);
    // 7. attn @ V (HMMA) -> bf16 hi/lo directly
    av2_k<<<dim3(NSEQ / 64, HH), 128>>>(bpost);

    // 8. out = oa @ W_out^T  (pipelined HMMA bf16x3)
    hmma_gemm<<<dim3(CDIM / 64, NSEQ / 128), 256, GEMM_SMEM>>>(
        (const bf16*)p_ahi, (const bf16*)p_alo,
        (const bf16*)p_ohi, (const bf16*)p_olo, out, CDIM, CDIM);
}

// round 13
// speedup vs baseline: 2.9949x; 1.2857x over previous
#include <cuda_runtime.h>
#include <cuda_bf16.h>
#include <math.h>
#include <cstdint>

#define NSEQ 2048
#define CDIM 1024
#define HH 16
#define DD 64
#define FDIM 3072

typedef __nv_bfloat16 bf16;

// ---------------- scratch (static device allocations; no cudaMalloc) --------
__device__ float g_qkv[NSEQ * FDIM];
__device__ float g_S [67108864];               // premixed scores fp32, 256 MB
__device__ float g_m [HH * NSEQ];
__device__ float g_l [HH * NSEQ];
__device__ float g_sumv[HH * DD];

// bf16 hi/lo operands
__device__ bf16 g_xhi[NSEQ * CDIM],  g_xlo[NSEQ * CDIM];
__device__ bf16 g_whi[FDIM * CDIM],  g_wlo[FDIM * CDIM];
__device__ bf16 g_ohi[CDIM * CDIM],  g_olo[CDIM * CDIM];   // W_out
__device__ bf16 g_ahi[NSEQ * CDIM],  g_alo[NSEQ * CDIM];   // attn@V output
__device__ bf16 g_qhi[HH * NSEQ * DD], g_qlo[HH * NSEQ * DD];
__device__ bf16 g_khi[HH * NSEQ * DD], g_klo[HH * NSEQ * DD];
__device__ bf16 g_vthi[HH * DD * NSEQ], g_vtlo[HH * DD * NSEQ];  // V^T [h][d][n]
__device__ bf16 g_Shi[67108864], g_Slo[67108864];                // attn bf16

// ---------------- helpers ----------------------------------------------------
__device__ __forceinline__ uint32_t smem_u32(const void* p) {
    uint32_t a;
    asm("{ .reg .u64 t; cvta.to.shared.u64 t, %1; cvt.u32.u64 %0, t; }"
        : "=r"(a) : "l"(p));
    return a;
}
__device__ __forceinline__ void cp16(uint32_t saddr, const void* gptr) {
    asm volatile("cp.async.ca.shared.global [%0], [%1], 16;"
                 :: "r"(saddr), "l"(gptr) : "memory");
}
__device__ __forceinline__ void mma_bf16(float* c, const uint32_t* a,
                                         const uint32_t* b)
{
    asm volatile(
        "mma.sync.aligned.m16n8k16.row.col.f32.bf16.bf16.f32 "
        "{%0,%1,%2,%3}, {%4,%5,%6,%7}, {%8,%9}, {%0,%1,%2,%3};"
        : "+f"(c[0]), "+f"(c[1]), "+f"(c[2]), "+f"(c[3])
        : "r"(a[0]), "r"(a[1]), "r"(a[2]), "r"(a[3]), "r"(b[0]), "r"(b[1]));
}

// ---------------- fp32 -> bf16 hi/lo split ----------------------------------
__global__ __launch_bounds__(256) void conv_split(
    const float* __restrict__ in, bf16* __restrict__ hi,
    bf16* __restrict__ lo, int n)
{
    int i = blockIdx.x * 256 + threadIdx.x;
    if (i >= n) return;
    float x = in[i];
    bf16 h = __float2bfloat16(x);
    hi[i] = h;
    lo[i] = __float2bfloat16(x - __bfloat162float(h));
}

// ---------------- pipelined warp-MMA bf16x3 GEMM, 128x128 tile --------------
// C[M,Nn] = A[M,K] * B[Nn,K]^T.  BK=32, 2-stage cp.async. 8 warps, warp=64x32.
#define STR2 40
#define SPLIT_B (128 * STR2 * 2)              // 10240 bytes per split
#define STAGE_BYTES (4 * SPLIT_B)             // 40960
#define GEMM_SMEM (2 * STAGE_BYTES)           // 81920

#define ISSUE_STAGE(stg, k0) do {                                          \
    uint32_t s_ = sbase + (stg) * STAGE_BYTES;                             \
    _Pragma("unroll")                                                      \
    for (int l_ = 0; l_ < 2; l_++) {                                       \
        int idx_ = tid + l_ * 256;                                         \
        int r_ = idx_ >> 2, c_ = idx_ & 3;                                 \
        uint32_t so_ = s_ + r_ * 80 + c_ * 16;                             \
        size_t g_ = (size_t)(bm * 128 + r_) * K + (k0) + c_ * 8;           \
        cp16(so_,           Ahi + g_);                                     \
        cp16(so_ + SPLIT_B, Alo + g_);                                     \
    }                                                                      \
    _Pragma("unroll")                                                      \
    for (int l_ = 0; l_ < 2; l_++) {                                       \
        int idx_ = tid + l_ * 256;                                         \
        int r_ = idx_ >> 2, c_ = idx_ & 3;                                 \
        uint32_t so_ = s_ + 2 * SPLIT_B + r_ * 80 + c_ * 16;               \
        size_t g_ = (size_t)(bn * 128 + r_) * K + (k0) + c_ * 8;           \
        cp16(so_,           Bhi + g_);                                     \
        cp16(so_ + SPLIT_B, Blo + g_);                                     \
    }                                                                      \
    asm volatile("cp.async.commit_group;" ::: "memory");                   \
} while (0)

__global__ __launch_bounds__(256) void hmma_gemm(
    const bf16* __restrict__ Ahi, const bf16* __restrict__ Alo,
    const bf16* __restrict__ Bhi, const bf16* __restrict__ Blo,
    float* __restrict__ C, int K, int ldc)
{
    extern __shared__ __align__(16) char sm[];
    uint32_t sbase = smem_u32(sm);

    int tid = threadIdx.x, lane = tid & 31, wid = tid >> 5;
    int wm = wid & 1, wn = wid >> 1;          // warp: rows 64*wm, cols 32*wn
    int bm = blockIdx.y, bn = blockIdx.x;
    int tq = lane >> 2, tk = (lane & 3) * 2;

    float acc[4][4][4] = {};

    ISSUE_STAGE(0, 0);
    int nch = K >> 5;
    for (int ch = 0; ch < nch; ch++) {
        if (ch + 1 < nch) {
            ISSUE_STAGE((ch + 1) & 1, (ch + 1) << 5);
            asm volatile("cp.async.wait_group 1;" ::: "memory");
        } else {
            asm volatile("cp.async.wait_group 0;" ::: "memory");
        }
        __syncthreads();

        const bf16* Ah = (const bf16*)(sm + (ch & 1) * STAGE_BYTES);
        const bf16* Al = Ah + 128 * STR2;
        const bf16* Bh = Al + 128 * STR2;
        const bf16* Bl = Bh + 128 * STR2;

        #pragma unroll
        for (int ks = 0; ks < 2; ks++) {
            int kc = ks * 16 + tk;
            uint32_t bhf[4][2], blf[4][2];
            #pragma unroll
            for (int nt = 0; nt < 4; nt++) {
                int r = (wn * 32 + nt * 8 + tq) * STR2;
                bhf[nt][0] = *(const uint32_t*)&Bh[r + kc];
                bhf[nt][1] = *(const uint32_t*)&Bh[r + kc + 8];
                blf[nt][0] = *(const uint32_t*)&Bl[r + kc];
                blf[nt][1] = *(const uint32_t*)&Bl[r + kc + 8];
            }
            #pragma unroll
            for (int mt = 0; mt < 4; mt++) {
                int m = (wm * 64 + mt * 16 + tq) * STR2;
                uint32_t ah[4], al[4];
                ah[0] = *(const uint32_t*)&Ah[m + kc];
                ah[1] = *(const uint32_t*)&Ah[m + 8 * STR2 + kc];
                ah[2] = *(const uint32_t*)&Ah[m + kc + 8];
                ah[3] = *(const uint32_t*)&Ah[m + 8 * STR2 + kc + 8];
                al[0] = *(const uint32_t*)&Al[m + kc];
                al[1] = *(const uint32_t*)&Al[m + 8 * STR2 + kc];
                al[2] = *(const uint32_t*)&Al[m + kc + 8];
                al[3] = *(const uint32_t*)&Al[m + 8 * STR2 + kc + 8];
                #pragma unroll
                for (int nt = 0; nt < 4; nt++) {
                    mma_bf16(acc[mt][nt], ah, bhf[nt]);
                    mma_bf16(acc[mt][nt], al, bhf[nt]);
                    mma_bf16(acc[mt][nt], ah, blf[nt]);
                }
            }
        }
        __syncthreads();
    }

    #pragma unroll
    for (int mt = 0; mt < 4; mt++) {
        int row = bm * 128 + wm * 64 + mt * 16 + tq;
        #pragma unroll
        for (int nt = 0; nt < 4; nt++) {
            int col = bn * 128 + wn * 32 + nt * 8 + tk;
            *(float2*)&C[(size_t)row * ldc + col] =
                make_float2(acc[mt][nt][0], acc[mt][nt][1]);
            *(float2*)&C[(size_t)(row + 8) * ldc + col] =
                make_float2(acc[mt][nt][2], acc[mt][nt][3]);
        }
    }
}

// ---------------- split qkv, l2-normalize -> bf16 hi/lo, emit kv ------------
__global__ void split_norm(float* __restrict__ kout, float* __restrict__ vout)
{
    int n = blockIdx.x, h = blockIdx.y, d = threadIdx.x;   // 64 threads
    int base = n * FDIM + (h * DD + d) * 3;
    float q = g_qkv[base + 0];
    float k = g_qkv[base + 1];
    float v = g_qkv[base + 2];

    float sq = q * q, sk = k * k;
    #pragma unroll
    for (int off = 16; off > 0; off >>= 1) {
        sq += __shfl_xor_sync(0xffffffffu, sq, off);
        sk += __shfl_xor_sync(0xffffffffu, sk, off);
    }
    __shared__ float red[4];
    int w = d >> 5, lane = d & 31;
    if (lane == 0) { red[w] = sq; red[2 + w] = sk; }
    __syncthreads();
    float nq = sqrtf(red[0] + red[1]);
    float nk = sqrtf(red[2] + red[3]);

    int o = (h * NSEQ + n) * DD + d;
    float qn = q / fmaxf(nq, 1e-12f);
    float kn = k / fmaxf(nk, 1e-12f);
    bf16 qh = __float2bfloat16(qn);
    bf16 kh = __float2bfloat16(kn);
    g_qhi[o] = qh; g_qlo[o] = __float2bfloat16(qn - __bfloat162float(qh));
    g_khi[o] = kh; g_klo[o] = __float2bfloat16(kn - __bfloat162float(kh));
    kout[o] = k;
    vout[o] = v;
}

// ---------------- V transpose: vout[h][n][d] -> vt[h][d][n] bf16 hi/lo ------
__global__ __launch_bounds__(256) void transpose_v(const float* __restrict__ vout)
{
    int h = blockIdx.z, n0 = blockIdx.x * 32, d0 = blockIdx.y * 32;
    __shared__ float t[32][33];
    int tid = threadIdx.x, tx = tid & 31, ty = tid >> 5;
    #pragma unroll
    for (int r = ty; r < 32; r += 8)
        t[r][tx] = vout[(size_t)(h * NSEQ + n0 + r) * DD + d0 + tx];
    __syncthreads();
    #pragma unroll
    for (int r = ty; r < 32; r += 8) {
        float v = t[tx][r];
        bf16 hv = __float2bfloat16(v);
        size_t o = (size_t)(h * DD + d0 + r) * NSEQ + n0 + tx;
        g_vthi[o] = hv;
        g_vtlo[o] = __float2bfloat16(v - __bfloat162float(hv));
    }
}

// ---------------- sum of V over sequence (for b_post term) -----------------
__global__ __launch_bounds__(256) void sumv_k(const float* __restrict__ vout)
{
    int h = blockIdx.x, tid = threadIdx.x;
    int d = tid & 63, seg = tid >> 6;
    float s = 0.f;
    for (int j = seg; j < NSEQ; j += 4)
        s += vout[(size_t)(h * NSEQ + j) * DD + d];
    __shared__ float red[256];
    red[tid] = s;
    __syncthreads();
    if (tid < 128) red[tid] += red[tid + 128];
    __syncthreads();
    if (tid < 64) g_sumv[h * DD + tid] = red[tid] + red[tid + 64];
}

// ---------------- fused dots(16 heads) + premix + pos_bias ------------------
// CTA = 32x32 causal tile, 8 warps (warp = m16n8 subtile). Loops all 16 heads
// with double-buffered cp.async Q/K tiles; mixed[16][4] accumulated in regs.
#define DSTR 72
__global__ __launch_bounds__(256) void dots16_k(
    const float* __restrict__ Wpre, const float* __restrict__ bpre,
    const float* __restrict__ pb, const float* __restrict__ temp_p)
{
    int jt = blockIdx.x, it = blockIdx.y;
    if (jt > it) return;

    __shared__ __align__(16) bf16 QH[2][32 * DSTR], QL[2][32 * DSTR];
    __shared__ __align__(16) bf16 KH[2][32 * DSTR], KL[2][32 * DSTR];
    __shared__ float w[256], bp[16];

    int tid = threadIdx.x, lane = tid & 31, wid = tid >> 5;
    float temp = __ldg(temp_p);
    w[tid] = Wpre[tid] * temp;
    if (tid < 16) bp[tid] = bpre[tid];

    int i0 = it * 32, j0 = jt * 32;
    int lr = tid >> 3, lc = (tid & 7) * 8;     // loader: row 0..31, col chunk

    #define D16_ISSUE(h, stg) do {                                          \
        size_t gq_ = (size_t)((h) * NSEQ + i0 + lr) * DD + lc;              \
        size_t gk_ = (size_t)((h) * NSEQ + j0 + lr) * DD + lc;              \
        uint32_t so_ = lr * (DSTR * 2) + lc * 2;                            \
        cp16(smem_u32(&QH[stg][0]) + so_, g_qhi + gq_);                     \
        cp16(smem_u32(&QL[stg][0]) + so_, g_qlo + gq_);                     \
        cp16(smem_u32(&KH[stg][0]) + so_, g_khi + gk_);                     \
        cp16(smem_u32(&KL[stg][0]) + so_, g_klo + gk_);                     \
        asm volatile("cp.async.commit_group;" ::: "memory");                \
    } while (0)

    D16_ISSUE(0, 0);

    int mo = (wid & 1) * 16, no = (wid >> 1) * 8;
    int tq = lane >> 2, tk = (lane & 3) * 2;

    float mixed[16][4] = {};

    for (int h = 0; h < 16; h++) {
        if (h < 15) {
            D16_ISSUE(h + 1, (h + 1) & 1);
            asm volatile("cp.async.wait_group 1;" ::: "memory");
        } else {
            asm volatile("cp.async.wait_group 0;" ::: "memory");
        }
        __syncthreads();

        const bf16* Qh = QH[h & 1];
        const bf16* Ql = QL[h & 1];
        const bf16* Kh = KH[h & 1];
        const bf16* Kl = KL[h & 1];

        float raw[4] = {};
        #pragma unroll
        for (int ki = 0; ki < 4; ki++) {
            int kc = ki * 16 + tk;
            uint32_t ah[4], al[4], bh[2], bl[2];
            ah[0] = *(const uint32_t*)&Qh[(mo + tq) * DSTR + kc];
            ah[1] = *(const uint32_t*)&Qh[(mo + tq + 8) * DSTR + kc];
            ah[2] = *(const uint32_t*)&Qh[(mo + tq) * DSTR + kc + 8];
            ah[3] = *(const uint32_t*)&Qh[(mo + tq + 8) * DSTR + kc + 8];
            al[0] = *(const uint32_t*)&Ql[(mo + tq) * DSTR + kc];
            al[1] = *(const uint32_t*)&Ql[(mo + tq + 8) * DSTR + kc];
            al[2] = *(const uint32_t*)&Ql[(mo + tq) * DSTR + kc + 8];
            al[3] = *(const uint32_t*)&Ql[(mo + tq + 8) * DSTR + kc + 8];
            bh[0] = *(const uint32_t*)&Kh[(no + tq) * DSTR + kc];
            bh[1] = *(const uint32_t*)&Kh[(no + tq) * DSTR + kc + 8];
            bl[0] = *(const uint32_t*)&Kl[(no + tq) * DSTR + kc];
            bl[1] = *(const uint32_t*)&Kl[(no + tq) * DSTR + kc + 8];
            mma_bf16(raw, ah, bh);
            mma_bf16(raw, al, bh);
            mma_bf16(raw, ah, bl);
        }
        __syncthreads();     // tile consumed; safe for h+2's issue next iter

        #pragma unroll
        for (int g = 0; g < 16; g++) {
            float wg = w[g * 16 + h];
            #pragma unroll
            for (int e = 0; e < 4; e++)
                mixed[g][e] = fmaf(wg, raw[e], mixed[g][e]);
        }
    }

    int row0 = i0 + mo + tq, col = j0 + no + tk;
    #pragma unroll
    for (int g = 0; g < 16; g++) {
        size_t b0 = ((size_t)(g * NSEQ + row0)) * NSEQ + col;
        size_t b1 = ((size_t)(g * NSEQ + row0 + 8)) * NSEQ + col;
        float2 p0 = *(const float2*)&pb[b0];
        float2 p1 = *(const float2*)&pb[b1];
        *(float2*)&g_S[b0] = make_float2(mixed[g][0] + bp[g] + p0.x,
                                         mixed[g][1] + bp[g] + p0.y);
        *(float2*)&g_S[b1] = make_float2(mixed[g][2] + bp[g] + p1.x,
                                         mixed[g][3] + bp[g] + p1.y);
    }
}

// ---------------- per-row online max / sum-exp ------------------------------
__global__ __launch_bounds__(256) void rowstat_k()
{
    int i = blockIdx.x, g = blockIdx.y;
    const float* row = g_S + ((size_t)(g * NSEQ + i)) * NSEQ;
    int tid = threadIdx.x;

    float m = -INFINITY, l = 0.f;
    for (int j = tid; j <= i; j += 256) {
        float s = row[j];
        float nm = fmaxf(m, s);
        l = l * __expf(m - nm) + __expf(s - nm);
        m = nm;
    }
    __shared__ float sm[256], sl[256];
    sm[tid] = m; sl[tid] = l;
    __syncthreads();
    for (int s = 128; s > 0; s >>= 1) {
        if (tid < s) {
            float m1 = sm[tid], l1 = sl[tid];
            float m2 = sm[tid + s], l2 = sl[tid + s];
            float M = fmaxf(m1, m2);
            float L = (M == -INFINITY) ? 0.f
                      : l1 * __expf(m1 - M) + l2 * __expf(m2 - M);
            sm[tid] = M; sl[tid] = L;
        }
        __syncthreads();
    }
    if (tid == 0) { g_m[g * NSEQ + i] = sm[0]; g_l[g * NSEQ + i] = sl[0]; }
}

// ---------------- softmax + post-mix -> attn bf16 hi/lo ---------------------
__global__ __launch_bounds__(256) void postmix_k(const float* __restrict__ Wpost)
{
    __shared__ float w[256];
    int tid = threadIdx.x;
    w[tid] = Wpost[tid];
    int i = blockIdx.y;
    int j = blockIdx.x * 256 + tid;
    __syncthreads();
    if (j > i) return;

    float a[16];
    #pragma unroll
    for (int h = 0; h < 16; h++) {
        float s = g_S[(size_t)(h * NSEQ + i) * NSEQ + j];
        a[h] = __expf(s - g_m[h * NSEQ + i]) / g_l[h * NSEQ + i];
    }
    #pragma unroll
    for (int g = 0; g < 16; g++) {
        float val = 0.f;
        #pragma unroll
        for (int h = 0; h < 16; h++) val = fmaf(w[g * 16 + h], a[h], val);
        size_t idx = (size_t)(g * NSEQ + i) * NSEQ + j;
        bf16 hv = __float2bfloat16(val);
        g_Shi[idx] = hv;
        g_Slo[idx] = __float2bfloat16(val - __bfloat162float(hv));
    }
}

// ---------------- HMMA attn @ V  -> bf16 hi/lo [n][(h d)] -------------------
#define TSTR 72
__global__ __launch_bounds__(128) void av2_k(const float* __restrict__ bpost)
{
    int it = blockIdx.x, h = blockIdx.y;
    int i0 = it * 64;
    __shared__ __align__(16) bf16 Ah[64 * TSTR], Al[64 * TSTR];
    __shared__ __align__(16) bf16 Bh[64 * TSTR], Bl[64 * TSTR];

    int tid = threadIdx.x, lane = tid & 31, wid = tid >> 5;
    int tq = lane >> 2, tk = (lane & 3) * 2;
    int m = wid * 16;

    float acc[8][4] = {};

    for (int j0 = 0; j0 <= i0; j0 += 64) {
        if (j0 < i0) {
            #pragma unroll
            for (int l = 0; l < 4; l++) {
                int idx = tid + l * 128;
                int r = idx >> 3, c8 = (idx & 7) * 8;
                size_t ga = (size_t)(h * NSEQ + i0 + r) * NSEQ + j0 + c8;
                *(uint4*)&Ah[r * TSTR + c8] = *(const uint4*)(g_Shi + ga);
                *(uint4*)&Al[r * TSTR + c8] = *(const uint4*)(g_Slo + ga);
            }
        } else {
            #pragma unroll 4
            for (int l = 0; l < 32; l++) {
                int idx = tid + l * 128;
                int r = idx >> 6, c = idx & 63;
                bool ok = (j0 + c) <= (i0 + r);
                size_t ga = (size_t)(h * NSEQ + i0 + r) * NSEQ + j0 + c;
                Ah[r * TSTR + c] = ok ? g_Shi[ga] : (bf16)__float2bfloat16(0.f);
                Al[r * TSTR + c] = ok ? g_Slo[ga] : (bf16)__float2bfloat16(0.f);
            }
        }
        #pragma unroll
        for (int l = 0; l < 4; l++) {
            int idx = tid + l * 128;
            int r = idx >> 3, c8 = (idx & 7) * 8;
            size_t gb = (size_t)(h * DD + r) * NSEQ + j0 + c8;
            *(uint4*)&Bh[r * TSTR + c8] = *(const uint4*)(g_vthi + gb);
            *(uint4*)&Bl[r * TSTR + c8] = *(const uint4*)(g_vtlo + gb);
        }
        __syncthreads();

        #pragma unroll
        for (int ki = 0; ki < 4; ki++) {
            int kk = ki * 16 + tk;
            uint32_t ah[4], al[4];
            ah[0] = *(const uint32_t*)&Ah[(m + tq) * TSTR + kk];
            ah[1] = *(const uint32_t*)&Ah[(m + tq + 8) * TSTR + kk];
            ah[2] = *(const uint32_t*)&Ah[(m + tq) * TSTR + kk + 8];
            ah[3] = *(const uint32_t*)&Ah[(m + tq + 8) * TSTR + kk + 8];
            al[0] = *(const uint32_t*)&Al[(m + tq) * TSTR + kk];
            al[1] = *(const uint32_t*)&Al[(m + tq + 8) * TSTR + kk];
            al[2] = *(const uint32_t*)&Al[(m + tq) * TSTR + kk + 8];
            al[3] = *(const uint32_t*)&Al[(m + tq + 8) * TSTR + kk + 8];
            #pragma unroll
            for (int n = 0; n < 8; n++) {
                uint32_t bh[2], bl[2];
                bh[0] = *(const uint32_t*)&Bh[(n * 8 + tq) * TSTR + kk];
                bh[1] = *(const uint32_t*)&Bh[(n * 8 + tq) * TSTR + kk + 8];
                bl[0] = *(const uint32_t*)&Bl[(n * 8 + tq) * TSTR + kk];
                bl[1] = *(const uint32_t*)&Bl[(n * 8 + tq) * TSTR + kk + 8];
                mma_bf16(acc[n], ah, bh);
                mma_bf16(acc[n], al, bh);
                mma_bf16(acc[n], ah, bl);
            }
        }
        __syncthreads();
    }

    float bpv = bpost[h];
    int row = i0 + m + tq;
    #pragma unroll
    for (int n = 0; n < 8; n++) {
        int d = n * 8 + tk;
        float s0 = bpv * g_sumv[h * DD + d];
        float s1 = bpv * g_sumv[h * DD + d + 1];
        float v00 = acc[n][0] + s0, v01 = acc[n][1] + s1;
        float v10 = acc[n][2] + s0, v11 = acc[n][3] + s1;
        size_t o0 = (size_t)row * CDIM + h * DD + d;
        size_t o1 = (size_t)(row + 8) * CDIM + h * DD + d;
        __nv_bfloat162 hi0, hi1, lo0, lo1;
        hi0.x = __float2bfloat16(v00); hi0.y = __float2bfloat16(v01);
        hi1.x = __float2bfloat16(v10); hi1.y = __float2bfloat16(v11);
        lo0.x = __float2bfloat16(v00 - __bfloat162float(hi0.x));
        lo0.y = __float2bfloat16(v01 - __bfloat162float(hi0.y));
        lo1.x = __float2bfloat16(v10 - __bfloat162float(hi1.x));
        lo1.y = __float2bfloat16(v11 - __bfloat162float(hi1.y));
        *(__nv_bfloat162*)&g_ahi[o0] = hi0;
        *(__nv_bfloat162*)&g_ahi[o1] = hi1;
        *(__nv_bfloat162*)&g_alo[o0] = lo0;
        *(__nv_bfloat162*)&g_alo[o1] = lo1;
    }
}

// ---------------- launch -----------------------------------------------------
extern "C" void kernel_launch(void* const* d_in, const int* in_sizes, int n_in,
                              void* d_out, int out_size)
{
    const float* x     = (const float*)d_in[0];
    const float* pb    = (const float*)d_in[1];
    // d_in[2] = mask: causal, applied analytically
    const float* Wqkv  = (const float*)d_in[3];
    const float* Wout  = (const float*)d_in[4];
    const float* temp  = (const float*)d_in[5];
    const float* Wpre  = (const float*)d_in[6];
    const float* bpre  = (const float*)d_in[7];
    const float* Wpost = (const float*)d_in[8];
    const float* bpost = (const float*)d_in[9];

    float* out  = (float*)d_out;                 // [2048, 1024]
    float* kout = out + NSEQ * CDIM;             // kv[0] = k  [16,2048,64]
    float* vout = kout + HH * NSEQ * DD;         // kv[1] = v

    cudaFuncSetAttribute(hmma_gemm,
        cudaFuncAttributeMaxDynamicSharedMemorySize, GEMM_SMEM);

    void* p_qkv;
    cudaGetSymbolAddress(&p_qkv, g_qkv);
    void *p_xhi, *p_xlo, *p_whi, *p_wlo, *p_ohi, *p_olo, *p_ahi, *p_alo;
    cudaGetSymbolAddress(&p_xhi, g_xhi); cudaGetSymbolAddress(&p_xlo, g_xlo);
    cudaGetSymbolAddress(&p_whi, g_whi); cudaGetSymbolAddress(&p_wlo, g_wlo);
    cudaGetSymbolAddress(&p_ohi, g_ohi); cudaGetSymbolAddress(&p_olo, g_olo);
    cudaGetSymbolAddress(&p_ahi, g_ahi); cudaGetSymbolAddress(&p_alo, g_alo);

    // 0. bf16 hi/lo splits of x, W_qkv, W_out
    conv_split<<<(NSEQ * CDIM) / 256, 256>>>(x, (bf16*)p_xhi, (bf16*)p_xlo,
                                             NSEQ * CDIM);
    conv_split<<<(FDIM * CDIM) / 256, 256>>>(Wqkv, (bf16*)p_whi, (bf16*)p_wlo,
                                             FDIM * CDIM);
    conv_split<<<(CDIM * CDIM) / 256, 256>>>(Wout, (bf16*)p_ohi, (bf16*)p_olo,
                                             CDIM * CDIM);

    // 1. qkv = x @ W_qkv^T  (pipelined HMMA bf16x3, 128x128)
    hmma_gemm<<<dim3(FDIM / 128, NSEQ / 128), 256, GEMM_SMEM>>>(
        (const bf16*)p_xhi, (const bf16*)p_xlo,
        (const bf16*)p_whi, (const bf16*)p_wlo, (float*)p_qkv, CDIM, FDIM);

    // 2. split + l2norm -> bf16 hi/lo; kv outputs
    split_norm<<<dim3(NSEQ, HH), 64>>>(kout, vout);
    // 3. V transpose -> bf16 hi/lo [h][d][n]; sum_j v
    transpose_v<<<dim3(NSEQ / 32, DD / 32, HH), 256>>>(vout);
    sumv_k<<<HH, 256>>>(vout);
    // 4. fused dots(16 heads) + premix + pos_bias -> premixed S
    dots16_k<<<dim3(NSEQ / 32, NSEQ / 32), 256>>>(Wpre, bpre, pb, temp);
    // 5. row max / sum-exp
    rowstat_k<<<dim3(NSEQ, HH), 256>>>();
    // 6. softmax + post-mix -> attn bf16 hi/lo
    postmix_k<<<dim3(NSEQ / 256, NSEQ), 256>>>(Wpost);
    // 7. attn @ V (HMMA) -> bf16 hi/lo directly
    av2_k<<<dim3(NSEQ / 64, HH), 128>>>(bpost);

    // 8. out = oa @ W_out^T  (pipelined HMMA bf16x3, 128x128)
    hmma_gemm<<<dim3(CDIM / 128, NSEQ / 128), 256, GEMM_SMEM>>>(
        (const bf16*)p_ahi, (const bf16*)p_alo,
        (const bf16*)p_ohi, (const bf16*)p_olo, out, CDIM, CDIM);
}

// round 14
// speedup vs baseline: 3.5265x; 1.1775x over previous
#include <cuda_runtime.h>
#include <cuda_bf16.h>
#include <math.h>
#include <cstdint>

#define NSEQ 2048
#define CDIM 1024
#define HH 16
#define DD 64
#define FDIM 3072

typedef __nv_bfloat16 bf16;

// ---------------- scratch (static device allocations; no cudaMalloc) --------
__device__ float g_qkv[NSEQ * FDIM];
__device__ float g_S [67108864];               // premixed scores fp32, 256 MB
__device__ float g_m [HH * NSEQ];
__device__ float g_l [HH * NSEQ];
__device__ float g_sumv[HH * DD];

// bf16 hi/lo operands
__device__ bf16 g_xhi[NSEQ * CDIM],  g_xlo[NSEQ * CDIM];
__device__ bf16 g_whi[FDIM * CDIM],  g_wlo[FDIM * CDIM];
__device__ bf16 g_ohi[CDIM * CDIM],  g_olo[CDIM * CDIM];   // W_out
__device__ bf16 g_ahi[NSEQ * CDIM],  g_alo[NSEQ * CDIM];   // attn@V output
__device__ bf16 g_qhi[HH * NSEQ * DD], g_qlo[HH * NSEQ * DD];
__device__ bf16 g_khi[HH * NSEQ * DD], g_klo[HH * NSEQ * DD];
__device__ bf16 g_vthi[HH * DD * NSEQ], g_vtlo[HH * DD * NSEQ];  // V^T [h][d][n]
__device__ bf16 g_Shi[67108864], g_Slo[67108864];                // attn bf16

// ---------------- helpers ----------------------------------------------------
__device__ __forceinline__ uint32_t smem_u32(const void* p) {
    uint32_t a;
    asm("{ .reg .u64 t; cvta.to.shared.u64 t, %1; cvt.u32.u64 %0, t; }"
        : "=r"(a) : "l"(p));
    return a;
}
__device__ __forceinline__ void cp16(uint32_t saddr, const void* gptr) {
    asm volatile("cp.async.ca.shared.global [%0], [%1], 16;"
                 :: "r"(saddr), "l"(gptr) : "memory");
}
__device__ __forceinline__ void mma_bf16(float* c, const uint32_t* a,
                                         const uint32_t* b)
{
    asm volatile(
        "mma.sync.aligned.m16n8k16.row.col.f32.bf16.bf16.f32 "
        "{%0,%1,%2,%3}, {%4,%5,%6,%7}, {%8,%9}, {%0,%1,%2,%3};"
        : "+f"(c[0]), "+f"(c[1]), "+f"(c[2]), "+f"(c[3])
        : "r"(a[0]), "r"(a[1]), "r"(a[2]), "r"(a[3]), "r"(b[0]), "r"(b[1]));
}

// ---------------- fp32 -> bf16 hi/lo split ----------------------------------
__global__ __launch_bounds__(256) void conv_split(
    const float* __restrict__ in, bf16* __restrict__ hi,
    bf16* __restrict__ lo, int n)
{
    int i = blockIdx.x * 256 + threadIdx.x;
    if (i >= n) return;
    float x = in[i];
    bf16 h = __float2bfloat16(x);
    hi[i] = h;
    lo[i] = __float2bfloat16(x - __bfloat162float(h));
}

// ---------------- pipelined warp-MMA bf16x3 GEMM, 128x128 tile, 3-stage -----
#define STR2 40
#define SPLIT_B (128 * STR2 * 2)              // 10240 bytes per split
#define STAGE_BYTES (4 * SPLIT_B)             // 40960
#define GEMM_SMEM (3 * STAGE_BYTES)           // 122880

#define ISSUE_STAGE(stg, k0) do {                                          \
    uint32_t s_ = sbase + (stg) * STAGE_BYTES;                             \
    _Pragma("unroll")                                                      \
    for (int l_ = 0; l_ < 2; l_++) {                                       \
        int idx_ = tid + l_ * 256;                                         \
        int r_ = idx_ >> 2, c_ = idx_ & 3;                                 \
        uint32_t so_ = s_ + r_ * 80 + c_ * 16;                             \
        size_t g_ = (size_t)(bm * 128 + r_) * K + (k0) + c_ * 8;           \
        cp16(so_,           Ahi + g_);                                     \
        cp16(so_ + SPLIT_B, Alo + g_);                                     \
    }                                                                      \
    _Pragma("unroll")                                                      \
    for (int l_ = 0; l_ < 2; l_++) {                                       \
        int idx_ = tid + l_ * 256;                                         \
        int r_ = idx_ >> 2, c_ = idx_ & 3;                                 \
        uint32_t so_ = s_ + 2 * SPLIT_B + r_ * 80 + c_ * 16;               \
        size_t g_ = (size_t)(bn * 128 + r_) * K + (k0) + c_ * 8;           \
        cp16(so_,           Bhi + g_);                                     \
        cp16(so_ + SPLIT_B, Blo + g_);                                     \
    }                                                                      \
    asm volatile("cp.async.commit_group;" ::: "memory");                   \
} while (0)

__global__ __launch_bounds__(256) void hmma_gemm(
    const bf16* __restrict__ Ahi, const bf16* __restrict__ Alo,
    const bf16* __restrict__ Bhi, const bf16* __restrict__ Blo,
    float* __restrict__ C, int K, int ldc)
{
    extern __shared__ __align__(16) char sm[];
    uint32_t sbase = smem_u32(sm);

    int tid = threadIdx.x, lane = tid & 31, wid = tid >> 5;
    int wm = wid & 1, wn = wid >> 1;
    int bm = blockIdx.y, bn = blockIdx.x;
    int tq = lane >> 2, tk = (lane & 3) * 2;

    float acc[4][4][4] = {};

    int nch = K >> 5;
    ISSUE_STAGE(0, 0);
    if (nch > 1) ISSUE_STAGE(1, 32);
    for (int ch = 0; ch < nch; ch++) {
        if (ch + 2 < nch) {
            ISSUE_STAGE((ch + 2) % 3, (ch + 2) << 5);
            asm volatile("cp.async.wait_group 2;" ::: "memory");
        } else if (ch + 1 < nch) {
            asm volatile("cp.async.wait_group 1;" ::: "memory");
        } else {
            asm volatile("cp.async.wait_group 0;" ::: "memory");
        }
        __syncthreads();

        const bf16* Ah = (const bf16*)(sm + (ch % 3) * STAGE_BYTES);
        const bf16* Al = Ah + 128 * STR2;
        const bf16* Bh = Al + 128 * STR2;
        const bf16* Bl = Bh + 128 * STR2;

        #pragma unroll
        for (int ks = 0; ks < 2; ks++) {
            int kc = ks * 16 + tk;
            uint32_t bhf[4][2], blf[4][2];
            #pragma unroll
            for (int nt = 0; nt < 4; nt++) {
                int r = (wn * 32 + nt * 8 + tq) * STR2;
                bhf[nt][0] = *(const uint32_t*)&Bh[r + kc];
                bhf[nt][1] = *(const uint32_t*)&Bh[r + kc + 8];
                blf[nt][0] = *(const uint32_t*)&Bl[r + kc];
                blf[nt][1] = *(const uint32_t*)&Bl[r + kc + 8];
            }
            #pragma unroll
            for (int mt = 0; mt < 4; mt++) {
                int m = (wm * 64 + mt * 16 + tq) * STR2;
                uint32_t ah[4], al[4];
                ah[0] = *(const uint32_t*)&Ah[m + kc];
                ah[1] = *(const uint32_t*)&Ah[m + 8 * STR2 + kc];
                ah[2] = *(const uint32_t*)&Ah[m + kc + 8];
                ah[3] = *(const uint32_t*)&Ah[m + 8 * STR2 + kc + 8];
                al[0] = *(const uint32_t*)&Al[m + kc];
                al[1] = *(const uint32_t*)&Al[m + 8 * STR2 + kc];
                al[2] = *(const uint32_t*)&Al[m + kc + 8];
                al[3] = *(const uint32_t*)&Al[m + 8 * STR2 + kc + 8];
                #pragma unroll
                for (int nt = 0; nt < 4; nt++) {
                    mma_bf16(acc[mt][nt], ah, bhf[nt]);
                    mma_bf16(acc[mt][nt], al, bhf[nt]);
                    mma_bf16(acc[mt][nt], ah, blf[nt]);
                }
            }
        }
        __syncthreads();
    }

    #pragma unroll
    for (int mt = 0; mt < 4; mt++) {
        int row = bm * 128 + wm * 64 + mt * 16 + tq;
        #pragma unroll
        for (int nt = 0; nt < 4; nt++) {
            int col = bn * 128 + wn * 32 + nt * 8 + tk;
            *(float2*)&C[(size_t)row * ldc + col] =
                make_float2(acc[mt][nt][0], acc[mt][nt][1]);
            *(float2*)&C[(size_t)(row + 8) * ldc + col] =
                make_float2(acc[mt][nt][2], acc[mt][nt][3]);
        }
    }
}

// ---------------- split qkv, l2-normalize -> bf16 hi/lo, emit kv ------------
__global__ void split_norm(float* __restrict__ kout, float* __restrict__ vout)
{
    int n = blockIdx.x, h = blockIdx.y, d = threadIdx.x;   // 64 threads
    int base = n * FDIM + (h * DD + d) * 3;
    float q = g_qkv[base + 0];
    float k = g_qkv[base + 1];
    float v = g_qkv[base + 2];

    float sq = q * q, sk = k * k;
    #pragma unroll
    for (int off = 16; off > 0; off >>= 1) {
        sq += __shfl_xor_sync(0xffffffffu, sq, off);
        sk += __shfl_xor_sync(0xffffffffu, sk, off);
    }
    __shared__ float red[4];
    int w = d >> 5, lane = d & 31;
    if (lane == 0) { red[w] = sq; red[2 + w] = sk; }
    __syncthreads();
    float nq = sqrtf(red[0] + red[1]);
    float nk = sqrtf(red[2] + red[3]);

    int o = (h * NSEQ + n) * DD + d;
    float qn = q / fmaxf(nq, 1e-12f);
    float kn = k / fmaxf(nk, 1e-12f);
    bf16 qh = __float2bfloat16(qn);
    bf16 kh = __float2bfloat16(kn);
    g_qhi[o] = qh; g_qlo[o] = __float2bfloat16(qn - __bfloat162float(qh));
    g_khi[o] = kh; g_klo[o] = __float2bfloat16(kn - __bfloat162float(kh));
    kout[o] = k;
    vout[o] = v;
}

// ---------------- V transpose: vout[h][n][d] -> vt[h][d][n] bf16 hi/lo ------
__global__ __launch_bounds__(256) void transpose_v(const float* __restrict__ vout)
{
    int h = blockIdx.z, n0 = blockIdx.x * 32, d0 = blockIdx.y * 32;
    __shared__ float t[32][33];
    int tid = threadIdx.x, tx = tid & 31, ty = tid >> 5;
    #pragma unroll
    for (int r = ty; r < 32; r += 8)
        t[r][tx] = vout[(size_t)(h * NSEQ + n0 + r) * DD + d0 + tx];
    __syncthreads();
    #pragma unroll
    for (int r = ty; r < 32; r += 8) {
        float v = t[tx][r];
        bf16 hv = __float2bfloat16(v);
        size_t o = (size_t)(h * DD + d0 + r) * NSEQ + n0 + tx;
        g_vthi[o] = hv;
        g_vtlo[o] = __float2bfloat16(v - __bfloat162float(hv));
    }
}

// ---------------- sum of V over sequence (for b_post term) -----------------
__global__ __launch_bounds__(256) void sumv_k(const float* __restrict__ vout)
{
    int h = blockIdx.x, tid = threadIdx.x;
    int d = tid & 63, seg = tid >> 6;
    float s = 0.f;
    for (int j = seg; j < NSEQ; j += 4)
        s += vout[(size_t)(h * NSEQ + j) * DD + d];
    __shared__ float red[256];
    red[tid] = s;
    __syncthreads();
    if (tid < 128) red[tid] += red[tid + 128];
    __syncthreads();
    if (tid < 64) g_sumv[h * DD + tid] = red[tid] + red[tid + 64];
}

// ---------------- fused dots(16 heads) + premix + pos_bias ------------------
#define DSTR 72
__global__ __launch_bounds__(256) void dots16_k(
    const float* __restrict__ Wpre, const float* __restrict__ bpre,
    const float* __restrict__ pb, const float* __restrict__ temp_p)
{
    int jt = blockIdx.x, it = blockIdx.y;
    if (jt > it) return;

    __shared__ __align__(16) bf16 QH[2][32 * DSTR], QL[2][32 * DSTR];
    __shared__ __align__(16) bf16 KH[2][32 * DSTR], KL[2][32 * DSTR];
    __shared__ float w[256], bp[16];

    int tid = threadIdx.x, lane = tid & 31, wid = tid >> 5;
    float temp = __ldg(temp_p);
    w[tid] = Wpre[tid] * temp;
    if (tid < 16) bp[tid] = bpre[tid];

    int i0 = it * 32, j0 = jt * 32;
    int lr = tid >> 3, lc = (tid & 7) * 8;

    #define D16_ISSUE(h, stg) do {                                          \
        size_t gq_ = (size_t)((h) * NSEQ + i0 + lr) * DD + lc;              \
        size_t gk_ = (size_t)((h) * NSEQ + j0 + lr) * DD + lc;              \
        uint32_t so_ = lr * (DSTR * 2) + lc * 2;                            \
        cp16(smem_u32(&QH[stg][0]) + so_, g_qhi + gq_);                     \
        cp16(smem_u32(&QL[stg][0]) + so_, g_qlo + gq_);                     \
        cp16(smem_u32(&KH[stg][0]) + so_, g_khi + gk_);                     \
        cp16(smem_u32(&KL[stg][0]) + so_, g_klo + gk_);                     \
        asm volatile("cp.async.commit_group;" ::: "memory");                \
    } while (0)

    D16_ISSUE(0, 0);

    int mo = (wid & 1) * 16, no = (wid >> 1) * 8;
    int tq = lane >> 2, tk = (lane & 3) * 2;

    float mixed[16][4] = {};

    for (int h = 0; h < 16; h++) {
        if (h < 15) {
            D16_ISSUE(h + 1, (h + 1) & 1);
            asm volatile("cp.async.wait_group 1;" ::: "memory");
        } else {
            asm volatile("cp.async.wait_group 0;" ::: "memory");
        }
        __syncthreads();

        const bf16* Qh = QH[h & 1];
        const bf16* Ql = QL[h & 1];
        const bf16* Kh = KH[h & 1];
        const bf16* Kl = KL[h & 1];

        float raw[4] = {};
        #pragma unroll
        for (int ki = 0; ki < 4; ki++) {
            int kc = ki * 16 + tk;
            uint32_t ah[4], al[4], bh[2], bl[2];
            ah[0] = *(const uint32_t*)&Qh[(mo + tq) * DSTR + kc];
            ah[1] = *(const uint32_t*)&Qh[(mo + tq + 8) * DSTR + kc];
            ah[2] = *(const uint32_t*)&Qh[(mo + tq) * DSTR + kc + 8];
            ah[3] = *(const uint32_t*)&Qh[(mo + tq + 8) * DSTR + kc + 8];
            al[0] = *(const uint32_t*)&Ql[(mo + tq) * DSTR + kc];
            al[1] = *(const uint32_t*)&Ql[(mo + tq + 8) * DSTR + kc];
            al[2] = *(const uint32_t*)&Ql[(mo + tq) * DSTR + kc + 8];
            al[3] = *(const uint32_t*)&Ql[(mo + tq + 8) * DSTR + kc + 8];
            bh[0] = *(const uint32_t*)&Kh[(no + tq) * DSTR + kc];
            bh[1] = *(const uint32_t*)&Kh[(no + tq) * DSTR + kc + 8];
            bl[0] = *(const uint32_t*)&Kl[(no + tq) * DSTR + kc];
            bl[1] = *(const uint32_t*)&Kl[(no + tq) * DSTR + kc + 8];
            mma_bf16(raw, ah, bh);
            mma_bf16(raw, al, bh);
            mma_bf16(raw, ah, bl);
        }
        __syncthreads();

        #pragma unroll
        for (int g = 0; g < 16; g++) {
            float wg = w[g * 16 + h];
            #pragma unroll
            for (int e = 0; e < 4; e++)
                mixed[g][e] = fmaf(wg, raw[e], mixed[g][e]);
        }
    }

    int row0 = i0 + mo + tq, col = j0 + no + tk;
    #pragma unroll
    for (int g = 0; g < 16; g++) {
        size_t b0 = ((size_t)(g * NSEQ + row0)) * NSEQ + col;
        size_t b1 = ((size_t)(g * NSEQ + row0 + 8)) * NSEQ + col;
        float2 p0 = *(const float2*)&pb[b0];
        float2 p1 = *(const float2*)&pb[b1];
        *(float2*)&g_S[b0] = make_float2(mixed[g][0] + bp[g] + p0.x,
                                         mixed[g][1] + bp[g] + p0.y);
        *(float2*)&g_S[b1] = make_float2(mixed[g][2] + bp[g] + p1.x,
                                         mixed[g][3] + bp[g] + p1.y);
    }
}

// ---------------- per-row online max / sum-exp (float4) ---------------------
__global__ __launch_bounds__(256) void rowstat_k()
{
    int i = blockIdx.x, g = blockIdx.y;
    const float* row = g_S + ((size_t)(g * NSEQ + i)) * NSEQ;
    int tid = threadIdx.x;

    float m = -INFINITY, l = 0.f;
    for (int j4 = tid * 4; j4 <= i; j4 += 1024) {
        float4 s4 = *(const float4*)&row[j4];
        float v0 = s4.x;
        float v1 = (j4 + 1 <= i) ? s4.y : -INFINITY;
        float v2 = (j4 + 2 <= i) ? s4.z : -INFINITY;
        float v3 = (j4 + 3 <= i) ? s4.w : -INFINITY;
        float mx = fmaxf(fmaxf(v0, v1), fmaxf(v2, v3));
        if (mx > m) { l *= __expf(m - mx); m = mx; }
        l += __expf(v0 - m) + __expf(v1 - m) + __expf(v2 - m) + __expf(v3 - m);
    }
    __shared__ float sm[256], sl[256];
    sm[tid] = m; sl[tid] = l;
    __syncthreads();
    for (int s = 128; s > 0; s >>= 1) {
        if (tid < s) {
            float m1 = sm[tid], l1 = sl[tid];
            float m2 = sm[tid + s], l2 = sl[tid + s];
            float M = fmaxf(m1, m2);
            float L = (M == -INFINITY) ? 0.f
                      : l1 * __expf(m1 - M) + l2 * __expf(m2 - M);
            sm[tid] = M; sl[tid] = L;
        }
        __syncthreads();
    }
    if (tid == 0) { g_m[g * NSEQ + i] = sm[0]; g_l[g * NSEQ + i] = sl[0]; }
}

// ---------------- softmax + post-mix -> attn bf16 hi/lo (2 j / thread) ------
__global__ __launch_bounds__(256) void postmix_k(const float* __restrict__ Wpost)
{
    __shared__ float w[256], sm_[16], sl_[16];
    int tid = threadIdx.x;
    int i = blockIdx.y;
    w[tid] = Wpost[tid];
    if (tid < 16) {
        sm_[tid] = g_m[tid * NSEQ + i];
        sl_[tid] = 1.f / g_l[tid * NSEQ + i];
    }
    __syncthreads();
    int j = blockIdx.x * 512 + tid * 2;
    if (j > i) return;
    bool two = (j + 1 <= i);

    float a0[16], a1[16];
    #pragma unroll
    for (int h = 0; h < 16; h++) {
        float2 s = *(const float2*)&g_S[(size_t)(h * NSEQ + i) * NSEQ + j];
        a0[h] = __expf(s.x - sm_[h]) * sl_[h];
        a1[h] = two ? __expf(s.y - sm_[h]) * sl_[h] : 0.f;
    }
    #pragma unroll
    for (int g = 0; g < 16; g++) {
        float v0 = 0.f, v1 = 0.f;
        #pragma unroll
        for (int h = 0; h < 16; h++) {
            float wg = w[g * 16 + h];
            v0 = fmaf(wg, a0[h], v0);
            v1 = fmaf(wg, a1[h], v1);
        }
        size_t idx = (size_t)(g * NSEQ + i) * NSEQ + j;
        bf16 h0 = __float2bfloat16(v0);
        bf16 h1 = __float2bfloat16(v1);
        if (two) {
            __nv_bfloat162 hi, lo;
            hi.x = h0; hi.y = h1;
            lo.x = __float2bfloat16(v0 - __bfloat162float(h0));
            lo.y = __float2bfloat16(v1 - __bfloat162float(h1));
            *(__nv_bfloat162*)&g_Shi[idx] = hi;
            *(__nv_bfloat162*)&g_Slo[idx] = lo;
        } else {
            g_Shi[idx] = h0;
            g_Slo[idx] = __float2bfloat16(v0 - __bfloat162float(h0));
        }
    }
}

// ---------------- HMMA attn @ V (2-stage cp.async) -> bf16 hi/lo ------------
#define TSTR 72
#define AV_SPL (64 * TSTR * 2)                 // 9216 bytes per array
#define AV_STAGE (4 * AV_SPL)                  // 36864
#define AV_SMEM (2 * AV_STAGE)                 // 73728

#define AV2_ISSUE(j0_, stg) do {                                            \
    uint32_t s_ = sbase + (stg) * AV_STAGE;                                 \
    _Pragma("unroll")                                                       \
    for (int l_ = 0; l_ < 4; l_++) {                                        \
        int idx_ = tid + l_ * 128;                                          \
        int r_ = idx_ >> 3, c_ = (idx_ & 7) * 8;                            \
        uint32_t so_ = s_ + r_ * (TSTR * 2) + c_ * 2;                       \
        size_t ga_ = (size_t)(h * NSEQ + i0 + r_) * NSEQ + (j0_) + c_;      \
        size_t gb_ = (size_t)(h * DD + r_) * NSEQ + (j0_) + c_;             \
        cp16(so_,              g_Shi + ga_);                                \
        cp16(so_ + AV_SPL,     g_Slo + ga_);                                \
        cp16(so_ + 2 * AV_SPL, g_vthi + gb_);                               \
        cp16(so_ + 3 * AV_SPL, g_vtlo + gb_);                               \
    }                                                                       \
    asm volatile("cp.async.commit_group;" ::: "memory");                    \
} while (0)

__global__ __launch_bounds__(128) void av2_k(const float* __restrict__ bpost)
{
    extern __shared__ __align__(16) char avsm[];
    uint32_t sbase = smem_u32(avsm);

    int it = blockIdx.x, h = blockIdx.y;
    int i0 = it * 64;
    int tid = threadIdx.x, lane = tid & 31, wid = tid >> 5;
    int tq = lane >> 2, tk = (lane & 3) * 2;
    int m = wid * 16;

    float acc[8][4] = {};
    int ntiles = it + 1;

    AV2_ISSUE(0, 0);
    for (int t = 0; t < ntiles; t++) {
        if (t + 1 < ntiles) {
            AV2_ISSUE((t + 1) * 64, (t + 1) & 1);
            asm volatile("cp.async.wait_group 1;" ::: "memory");
        } else {
            asm volatile("cp.async.wait_group 0;" ::: "memory");
        }
        __syncthreads();

        bf16* Ah = (bf16*)(avsm + (t & 1) * AV_STAGE);
        bf16* Al = Ah + 64 * TSTR;
        const bf16* Bh = Al + 64 * TSTR;
        const bf16* Bl = Bh + 64 * TSTR;

        if (t == it) {   // diagonal tile: zero upper triangle (j > i)
            bf16 z = __float2bfloat16(0.f);
            #pragma unroll 8
            for (int l = 0; l < 32; l++) {
                int idx = tid + l * 128;
                int r = idx >> 6, c = idx & 63;
                if (c > r) { Ah[r * TSTR + c] = z; Al[r * TSTR + c] = z; }
            }
            __syncthreads();
        }

        #pragma unroll
        for (int ki = 0; ki < 4; ki++) {
            int kk = ki * 16 + tk;
            uint32_t ah[4], al[4];
            ah[0] = *(const uint32_t*)&Ah[(m + tq) * TSTR + kk];
            ah[1] = *(const uint32_t*)&Ah[(m + tq + 8) * TSTR + kk];
            ah[2] = *(const uint32_t*)&Ah[(m + tq) * TSTR + kk + 8];
            ah[3] = *(const uint32_t*)&Ah[(m + tq + 8) * TSTR + kk + 8];
            al[0] = *(const uint32_t*)&Al[(m + tq) * TSTR + kk];
            al[1] = *(const uint32_t*)&Al[(m + tq + 8) * TSTR + kk];
            al[2] = *(const uint32_t*)&Al[(m + tq) * TSTR + kk + 8];
            al[3] = *(const uint32_t*)&Al[(m + tq + 8) * TSTR + kk + 8];
            #pragma unroll
            for (int n = 0; n < 8; n++) {
                uint32_t bh[2], bl[2];
                bh[0] = *(const uint32_t*)&Bh[(n * 8 + tq) * TSTR + kk];
                bh[1] = *(const uint32_t*)&Bh[(n * 8 + tq) * TSTR + kk + 8];
                bl[0] = *(const uint32_t*)&Bl[(n * 8 + tq) * TSTR + kk];
                bl[1] = *(const uint32_t*)&Bl[(n * 8 + tq) * TSTR + kk + 8];
                mma_bf16(acc[n], ah, bh);
                mma_bf16(acc[n], al, bh);
                mma_bf16(acc[n], ah, bl);
            }
        }
        __syncthreads();
    }

    float bpv = bpost[h];
    int row = i0 + m + tq;
    #pragma unroll
    for (int n = 0; n < 8; n++) {
        int d = n * 8 + tk;
        float s0 = bpv * g_sumv[h * DD + d];
        float s1 = bpv * g_sumv[h * DD + d + 1];
        float v00 = acc[n][0] + s0, v01 = acc[n][1] + s1;
        float v10 = acc[n][2] + s0, v11 = acc[n][3] + s1;
        size_t o0 = (size_t)row * CDIM + h * DD + d;
        size_t o1 = (size_t)(row + 8) * CDIM + h * DD + d;
        __nv_bfloat162 hi0, hi1, lo0, lo1;
        hi0.x = __float2bfloat16(v00); hi0.y = __float2bfloat16(v01);
        hi1.x = __float2bfloat16(v10); hi1.y = __float2bfloat16(v11);
        lo0.x = __float2bfloat16(v00 - __bfloat162float(hi0.x));
        lo0.y = __float2bfloat16(v01 - __bfloat162float(hi0.y));
        lo1.x = __float2bfloat16(v10 - __bfloat162float(hi1.x));
        lo1.y = __float2bfloat16(v11 - __bfloat162float(hi1.y));
        *(__nv_bfloat162*)&g_ahi[o0] = hi0;
        *(__nv_bfloat162*)&g_ahi[o1] = hi1;
        *(__nv_bfloat162*)&g_alo[o0] = lo0;
        *(__nv_bfloat162*)&g_alo[o1] = lo1;
    }
}

// ---------------- launch -----------------------------------------------------
extern "C" void kernel_launch(void* const* d_in, const int* in_sizes, int n_in,
                              void* d_out, int out_size)
{
    const float* x     = (const float*)d_in[0];
    const float* pb    = (const float*)d_in[1];
    // d_in[2] = mask: causal, applied analytically
    const float* Wqkv  = (const float*)d_in[3];
    const float* Wout  = (const float*)d_in[4];
    const float* temp  = (const float*)d_in[5];
    const float* Wpre  = (const float*)d_in[6];
    const float* bpre  = (const float*)d_in[7];
    const float* Wpost = (const float*)d_in[8];
    const float* bpost = (const float*)d_in[9];

    float* out  = (float*)d_out;                 // [2048, 1024]
    float* kout = out + NSEQ * CDIM;             // kv[0] = k  [16,2048,64]
    float* vout = kout + HH * NSEQ * DD;         // kv[1] = v

    cudaFuncSetAttribute(hmma_gemm,
        cudaFuncAttributeMaxDynamicSharedMemorySize, GEMM_SMEM);
    cudaFuncSetAttribute(av2_k,
        cudaFuncAttributeMaxDynamicSharedMemorySize, AV_SMEM);

    void* p_qkv;
    cudaGetSymbolAddress(&p_qkv, g_qkv);
    void *p_xhi, *p_xlo, *p_whi, *p_wlo, *p_ohi, *p_olo, *p_ahi, *p_alo;
    cudaGetSymbolAddress(&p_xhi, g_xhi); cudaGetSymbolAddress(&p_xlo, g_xlo);
    cudaGetSymbolAddress(&p_whi, g_whi); cudaGetSymbolAddress(&p_wlo, g_wlo);
    cudaGetSymbolAddress(&p_ohi, g_ohi); cudaGetSymbolAddress(&p_olo, g_olo);
    cudaGetSymbolAddress(&p_ahi, g_ahi); cudaGetSymbolAddress(&p_alo, g_alo);

    // 0. bf16 hi/lo splits of x, W_qkv, W_out
    conv_split<<<(NSEQ * CDIM) / 256, 256>>>(x, (bf16*)p_xhi, (bf16*)p_xlo,
                                             NSEQ * CDIM);
    conv_split<<<(FDIM * CDIM) / 256, 256>>>(Wqkv, (bf16*)p_whi, (bf16*)p_wlo,
                                             FDIM * CDIM);
    conv_split<<<(CDIM * CDIM) / 256, 256>>>(Wout, (bf16*)p_ohi, (bf16*)p_olo,
                                             CDIM * CDIM);

    // 1. qkv = x @ W_qkv^T  (3-stage pipelined HMMA bf16x3, 128x128)
    hmma_gemm<<<dim3(FDIM / 128, NSEQ / 128), 256, GEMM_SMEM>>>(
        (const bf16*)p_xhi, (const bf16*)p_xlo,
        (const bf16*)p_whi, (const bf16*)p_wlo, (float*)p_qkv, CDIM, FDIM);

    // 2. split + l2norm -> bf16 hi/lo; kv outputs
    split_norm<<<dim3(NSEQ, HH), 64>>>(kout, vout);
    // 3. V transpose -> bf16 hi/lo [h][d][n]; sum_j v
    transpose_v<<<dim3(NSEQ / 32, DD / 32, HH), 256>>>(vout);
    sumv_k<<<HH, 256>>>(vout);
    // 4. fused dots(16 heads) + premix + pos_bias -> premixed S
    dots16_k<<<dim3(NSEQ / 32, NSEQ / 32), 256>>>(Wpre, bpre, pb, temp);
    // 5. row max / sum-exp (float4)
    rowstat_k<<<dim3(NSEQ, HH), 256>>>();
    // 6. softmax + post-mix -> attn bf16 hi/lo (2 j / thread)
    postmix_k<<<dim3(NSEQ / 512, NSEQ), 256>>>(Wpost);
    // 7. attn @ V (2-stage pipelined HMMA) -> bf16 hi/lo directly
    av2_k<<<dim3(NSEQ / 64, HH), 128, AV_SMEM>>>(bpost);

    // 8. out = oa @ W_out^T  (3-stage pipelined HMMA bf16x3, 128x128)
    hmma_gemm<<<dim3(CDIM / 128, NSEQ / 128), 256, GEMM_SMEM>>>(
        (const bf16*)p_ahi, (const bf16*)p_alo,
        (const bf16*)p_ohi, (const bf16*)p_olo, out, CDIM, CDIM);
}

// round 15
// speedup vs baseline: 3.6875x; 1.0456x over previous
#include <cuda_runtime.h>
#include <cuda_bf16.h>
#include <math.h>
#include <cstdint>

#define NSEQ 2048
#define CDIM 1024
#define HH 16
#define DD 64
#define FDIM 3072

typedef __nv_bfloat16 bf16;

// ---------------- scratch (static device allocations; no cudaMalloc) --------
__device__ float g_qkv[NSEQ * FDIM];
__device__ float g_S [67108864];               // premixed scores fp32, 256 MB
__device__ float g_m [HH * NSEQ];
__device__ float g_l [HH * NSEQ];
__device__ float g_sumv[HH * DD];

// bf16 hi/lo operands
__device__ bf16 g_xhi[NSEQ * CDIM],  g_xlo[NSEQ * CDIM];
__device__ bf16 g_whi[FDIM * CDIM],  g_wlo[FDIM * CDIM];
__device__ bf16 g_ohi[CDIM * CDIM],  g_olo[CDIM * CDIM];   // W_out
__device__ bf16 g_ahi[NSEQ * CDIM],  g_alo[NSEQ * CDIM];   // attn@V output
__device__ bf16 g_qhi[HH * NSEQ * DD], g_qlo[HH * NSEQ * DD];
__device__ bf16 g_khi[HH * NSEQ * DD], g_klo[HH * NSEQ * DD];
__device__ bf16 g_vthi[HH * DD * NSEQ], g_vtlo[HH * DD * NSEQ];  // V^T [h][d][n]
__device__ bf16 g_Shi[67108864], g_Slo[67108864];                // attn bf16

// ---------------- helpers ----------------------------------------------------
__device__ __forceinline__ uint32_t smem_u32(const void* p) {
    uint32_t a;
    asm("{ .reg .u64 t; cvta.to.shared.u64 t, %1; cvt.u32.u64 %0, t; }"
        : "=r"(a) : "l"(p));
    return a;
}
__device__ __forceinline__ void cp16(uint32_t saddr, const void* gptr) {
    asm volatile("cp.async.ca.shared.global [%0], [%1], 16;"
                 :: "r"(saddr), "l"(gptr) : "memory");
}
__device__ __forceinline__ void mma_bf16(float* c, const uint32_t* a,
                                         const uint32_t* b)
{
    asm volatile(
        "mma.sync.aligned.m16n8k16.row.col.f32.bf16.bf16.f32 "
        "{%0,%1,%2,%3}, {%4,%5,%6,%7}, {%8,%9}, {%0,%1,%2,%3};"
        : "+f"(c[0]), "+f"(c[1]), "+f"(c[2]), "+f"(c[3])
        : "r"(a[0]), "r"(a[1]), "r"(a[2]), "r"(a[3]), "r"(b[0]), "r"(b[1]));
}
__device__ __forceinline__ void ldsm_x4(uint32_t* r, uint32_t saddr) {
    asm volatile("ldmatrix.sync.aligned.m8n8.x4.shared.b16 {%0,%1,%2,%3}, [%4];"
        : "=r"(r[0]), "=r"(r[1]), "=r"(r[2]), "=r"(r[3]) : "r"(saddr));
}
__device__ __forceinline__ void ldsm_x2(uint32_t* r, uint32_t saddr) {
    asm volatile("ldmatrix.sync.aligned.m8n8.x2.shared.b16 {%0,%1}, [%2];"
        : "=r"(r[0]), "=r"(r[1]) : "r"(saddr));
}

// ---------------- fp32 -> bf16 hi/lo split ----------------------------------
__global__ __launch_bounds__(256) void conv_split(
    const float* __restrict__ in, bf16* __restrict__ hi,
    bf16* __restrict__ lo, int n)
{
    int i = blockIdx.x * 256 + threadIdx.x;
    if (i >= n) return;
    float x = in[i];
    bf16 h = __float2bfloat16(x);
    hi[i] = h;
    lo[i] = __float2bfloat16(x - __bfloat162float(h));
}

// ---------------- pipelined warp-MMA bf16x3 GEMM, 128x128 tile, 3-stage -----
#define STR2 40
#define SPLIT_B (128 * STR2 * 2)              // 10240 bytes per split
#define STAGE_BYTES (4 * SPLIT_B)             // 40960
#define GEMM_SMEM (3 * STAGE_BYTES)           // 122880

#define ISSUE_STAGE(stg, k0) do {                                          \
    uint32_t s_ = sbase + (stg) * STAGE_BYTES;                             \
    _Pragma("unroll")                                                      \
    for (int l_ = 0; l_ < 2; l_++) {                                       \
        int idx_ = tid + l_ * 256;                                         \
        int r_ = idx_ >> 2, c_ = idx_ & 3;                                 \
        uint32_t so_ = s_ + r_ * 80 + c_ * 16;                             \
        size_t g_ = (size_t)(bm * 128 + r_) * K + (k0) + c_ * 8;           \
        cp16(so_,           Ahi + g_);                                     \
        cp16(so_ + SPLIT_B, Alo + g_);                                     \
    }                                                                      \
    _Pragma("unroll")                                                      \
    for (int l_ = 0; l_ < 2; l_++) {                                       \
        int idx_ = tid + l_ * 256;                                         \
        int r_ = idx_ >> 2, c_ = idx_ & 3;                                 \
        uint32_t so_ = s_ + 2 * SPLIT_B + r_ * 80 + c_ * 16;               \
        size_t g_ = (size_t)(bn * 128 + r_) * K + (k0) + c_ * 8;           \
        cp16(so_,           Bhi + g_);                                     \
        cp16(so_ + SPLIT_B, Blo + g_);                                     \
    }                                                                      \
    asm volatile("cp.async.commit_group;" ::: "memory");                   \
} while (0)

__global__ __launch_bounds__(256) void hmma_gemm(
    const bf16* __restrict__ Ahi, const bf16* __restrict__ Alo,
    const bf16* __restrict__ Bhi, const bf16* __restrict__ Blo,
    float* __restrict__ C, int K, int ldc)
{
    extern __shared__ __align__(16) char sm[];
    uint32_t sbase = smem_u32(sm);

    int tid = threadIdx.x, lane = tid & 31, wid = tid >> 5;
    int wm = wid & 1, wn = wid >> 1;
    int bm = blockIdx.y, bn = blockIdx.x;
    int tq = lane >> 2, tk = (lane & 3) * 2;

    // ldmatrix per-lane byte offsets (row stride STR2 bf16 = 80 B)
    uint32_t a_lane = ((lane & 15) * STR2 + (lane >> 4) * 8) * 2;
    uint32_t b_lane = (((lane & 7) + ((lane >> 4) << 3)) * STR2
                       + ((lane >> 3) & 1) * 8) * 2;

    float acc[4][4][4] = {};

    int nch = K >> 5;
    ISSUE_STAGE(0, 0);
    if (nch > 1) ISSUE_STAGE(1, 32);
    for (int ch = 0; ch < nch; ch++) {
        if (ch + 2 < nch) {
            ISSUE_STAGE((ch + 2) % 3, (ch + 2) << 5);
            asm volatile("cp.async.wait_group 2;" ::: "memory");
        } else if (ch + 1 < nch) {
            asm volatile("cp.async.wait_group 1;" ::: "memory");
        } else {
            asm volatile("cp.async.wait_group 0;" ::: "memory");
        }
        __syncthreads();

        uint32_t stg = sbase + (ch % 3) * STAGE_BYTES;

        #pragma unroll
        for (int ks = 0; ks < 2; ks++) {
            uint32_t koff = ks * 32;   // 16 bf16 = 32 bytes
            uint32_t bhf[4][2], blf[4][2];
            #pragma unroll
            for (int np = 0; np < 2; np++) {
                uint32_t boff = (uint32_t)((wn * 32 + np * 16) * STR2) * 2
                                + koff + b_lane;
                uint32_t r[4];
                ldsm_x4(r, stg + 2 * SPLIT_B + boff);
                bhf[2 * np][0] = r[0]; bhf[2 * np][1] = r[1];
                bhf[2 * np + 1][0] = r[2]; bhf[2 * np + 1][1] = r[3];
                ldsm_x4(r, stg + 3 * SPLIT_B + boff);
                blf[2 * np][0] = r[0]; blf[2 * np][1] = r[1];
                blf[2 * np + 1][0] = r[2]; blf[2 * np + 1][1] = r[3];
            }
            #pragma unroll
            for (int mt = 0; mt < 4; mt++) {
                uint32_t aoff = (uint32_t)((wm * 64 + mt * 16) * STR2) * 2
                                + koff + a_lane;
                uint32_t ah[4], al[4];
                ldsm_x4(ah, stg + aoff);
                ldsm_x4(al, stg + SPLIT_B + aoff);
                #pragma unroll
                for (int nt = 0; nt < 4; nt++) {
                    mma_bf16(acc[mt][nt], ah, bhf[nt]);
                    mma_bf16(acc[mt][nt], al, bhf[nt]);
                    mma_bf16(acc[mt][nt], ah, blf[nt]);
                }
            }
        }
        __syncthreads();
    }

    #pragma unroll
    for (int mt = 0; mt < 4; mt++) {
        int row = bm * 128 + wm * 64 + mt * 16 + tq;
        #pragma unroll
        for (int nt = 0; nt < 4; nt++) {
            int col = bn * 128 + wn * 32 + nt * 8 + tk;
            *(float2*)&C[(size_t)row * ldc + col] =
                make_float2(acc[mt][nt][0], acc[mt][nt][1]);
            *(float2*)&C[(size_t)(row + 8) * ldc + col] =
                make_float2(acc[mt][nt][2], acc[mt][nt][3]);
        }
    }
}

// ---------------- split qkv, l2-normalize -> bf16 hi/lo, emit kv ------------
__global__ void split_norm(float* __restrict__ kout, float* __restrict__ vout)
{
    int n = blockIdx.x, h = blockIdx.y, d = threadIdx.x;   // 64 threads
    int base = n * FDIM + (h * DD + d) * 3;
    float q = g_qkv[base + 0];
    float k = g_qkv[base + 1];
    float v = g_qkv[base + 2];

    float sq = q * q, sk = k * k;
    #pragma unroll
    for (int off = 16; off > 0; off >>= 1) {
        sq += __shfl_xor_sync(0xffffffffu, sq, off);
        sk += __shfl_xor_sync(0xffffffffu, sk, off);
    }
    __shared__ float red[4];
    int w = d >> 5, lane = d & 31;
    if (lane == 0) { red[w] = sq; red[2 + w] = sk; }
    __syncthreads();
    float nq = sqrtf(red[0] + red[1]);
    float nk = sqrtf(red[2] + red[3]);

    int o = (h * NSEQ + n) * DD + d;
    float qn = q / fmaxf(nq, 1e-12f);
    float kn = k / fmaxf(nk, 1e-12f);
    bf16 qh = __float2bfloat16(qn);
    bf16 kh = __float2bfloat16(kn);
    g_qhi[o] = qh; g_qlo[o] = __float2bfloat16(qn - __bfloat162float(qh));
    g_khi[o] = kh; g_klo[o] = __float2bfloat16(kn - __bfloat162float(kh));
    kout[o] = k;
    vout[o] = v;
}

// ---------------- V transpose: vout[h][n][d] -> vt[h][d][n] bf16 hi/lo ------
__global__ __launch_bounds__(256) void transpose_v(const float* __restrict__ vout)
{
    int h = blockIdx.z, n0 = blockIdx.x * 32, d0 = blockIdx.y * 32;
    __shared__ float t[32][33];
    int tid = threadIdx.x, tx = tid & 31, ty = tid >> 5;
    #pragma unroll
    for (int r = ty; r < 32; r += 8)
        t[r][tx] = vout[(size_t)(h * NSEQ + n0 + r) * DD + d0 + tx];
    __syncthreads();
    #pragma unroll
    for (int r = ty; r < 32; r += 8) {
        float v = t[tx][r];
        bf16 hv = __float2bfloat16(v);
        size_t o = (size_t)(h * DD + d0 + r) * NSEQ + n0 + tx;
        g_vthi[o] = hv;
        g_vtlo[o] = __float2bfloat16(v - __bfloat162float(hv));
    }
}

// ---------------- sum of V over sequence (for b_post term) -----------------
__global__ __launch_bounds__(256) void sumv_k(const float* __restrict__ vout)
{
    int h = blockIdx.x, tid = threadIdx.x;
    int d = tid & 63, seg = tid >> 6;
    float s = 0.f;
    for (int j = seg; j < NSEQ; j += 4)
        s += vout[(size_t)(h * NSEQ + j) * DD + d];
    __shared__ float red[256];
    red[tid] = s;
    __syncthreads();
    if (tid < 128) red[tid] += red[tid + 128];
    __syncthreads();
    if (tid < 64) g_sumv[h * DD + tid] = red[tid] + red[tid + 64];
}

// ---------------- fused dots(16 heads) + premix + pos_bias ------------------
#define DSTR 72
__global__ __launch_bounds__(256) void dots16_k(
    const float* __restrict__ Wpre, const float* __restrict__ bpre,
    const float* __restrict__ pb, const float* __restrict__ temp_p)
{
    int jt = blockIdx.x, it = blockIdx.y;
    if (jt > it) return;

    __shared__ __align__(16) bf16 QH[2][32 * DSTR], QL[2][32 * DSTR];
    __shared__ __align__(16) bf16 KH[2][32 * DSTR], KL[2][32 * DSTR];
    __shared__ float w[256], bp[16];

    int tid = threadIdx.x, lane = tid & 31, wid = tid >> 5;
    float temp = __ldg(temp_p);
    w[tid] = Wpre[tid] * temp;
    if (tid < 16) bp[tid] = bpre[tid];

    int i0 = it * 32, j0 = jt * 32;
    int lr = tid >> 3, lc = (tid & 7) * 8;

    #define D16_ISSUE(h, stg) do {                                          \
        size_t gq_ = (size_t)((h) * NSEQ + i0 + lr) * DD + lc;              \
        size_t gk_ = (size_t)((h) * NSEQ + j0 + lr) * DD + lc;              \
        uint32_t so_ = lr * (DSTR * 2) + lc * 2;                            \
        cp16(smem_u32(&QH[stg][0]) + so_, g_qhi + gq_);                     \
        cp16(smem_u32(&QL[stg][0]) + so_, g_qlo + gq_);                     \
        cp16(smem_u32(&KH[stg][0]) + so_, g_khi + gk_);                     \
        cp16(smem_u32(&KL[stg][0]) + so_, g_klo + gk_);                     \
        asm volatile("cp.async.commit_group;" ::: "memory");                \
    } while (0)

    D16_ISSUE(0, 0);

    int mo = (wid & 1) * 16, no = (wid >> 1) * 8;
    int tq = lane >> 2, tk = (lane & 3) * 2;

    // ldmatrix lane offsets (row stride DSTR bf16 = 144 B)
    uint32_t a_lane = ((lane & 15) * DSTR + (lane >> 4) * 8) * 2;
    int l4 = lane & 15;
    uint32_t b_lane = ((l4 & 7) * DSTR + ((l4 >> 3) & 1) * 8) * 2;

    float mixed[16][4] = {};

    for (int h = 0; h < 16; h++) {
        if (h < 15) {
            D16_ISSUE(h + 1, (h + 1) & 1);
            asm volatile("cp.async.wait_group 1;" ::: "memory");
        } else {
            asm volatile("cp.async.wait_group 0;" ::: "memory");
        }
        __syncthreads();

        uint32_t qh_b = smem_u32(&QH[h & 1][0]) + (uint32_t)(mo * DSTR * 2);
        uint32_t ql_b = smem_u32(&QL[h & 1][0]) + (uint32_t)(mo * DSTR * 2);
        uint32_t kh_b = smem_u32(&KH[h & 1][0]) + (uint32_t)(no * DSTR * 2);
        uint32_t kl_b = smem_u32(&KL[h & 1][0]) + (uint32_t)(no * DSTR * 2);

        float raw[4] = {};
        #pragma unroll
        for (int ki = 0; ki < 4; ki++) {
            uint32_t koff = ki * 32;
            uint32_t ah[4], al[4], bh[2], bl[2];
            ldsm_x4(ah, qh_b + koff + a_lane);
            ldsm_x4(al, ql_b + koff + a_lane);
            ldsm_x2(bh, kh_b + koff + b_lane);
            ldsm_x2(bl, kl_b + koff + b_lane);
            mma_bf16(raw, ah, bh);
            mma_bf16(raw, al, bh);
            mma_bf16(raw, ah, bl);
        }
        __syncthreads();

        #pragma unroll
        for (int g = 0; g < 16; g++) {
            float wg = w[g * 16 + h];
            #pragma unroll
            for (int e = 0; e < 4; e++)
                mixed[g][e] = fmaf(wg, raw[e], mixed[g][e]);
        }
    }

    int row0 = i0 + mo + tq, col = j0 + no + tk;
    #pragma unroll
    for (int g = 0; g < 16; g++) {
        size_t b0 = ((size_t)(g * NSEQ + row0)) * NSEQ + col;
        size_t b1 = ((size_t)(g * NSEQ + row0 + 8)) * NSEQ + col;
        float2 p0 = *(const float2*)&pb[b0];
        float2 p1 = *(const float2*)&pb[b1];
        *(float2*)&g_S[b0] = make_float2(mixed[g][0] + bp[g] + p0.x,
                                         mixed[g][1] + bp[g] + p0.y);
        *(float2*)&g_S[b1] = make_float2(mixed[g][2] + bp[g] + p1.x,
                                         mixed[g][3] + bp[g] + p1.y);
    }
}

// ---------------- per-row online max / sum-exp (float4) ---------------------
__global__ __launch_bounds__(256) void rowstat_k()
{
    int i = blockIdx.x, g = blockIdx.y;
    const float* row = g_S + ((size_t)(g * NSEQ + i)) * NSEQ;
    int tid = threadIdx.x;

    float m = -INFINITY, l = 0.f;
    for (int j4 = tid * 4; j4 <= i; j4 += 1024) {
        float4 s4 = *(const float4*)&row[j4];
        float v0 = s4.x;
        float v1 = (j4 + 1 <= i) ? s4.y : -INFINITY;
        float v2 = (j4 + 2 <= i) ? s4.z : -INFINITY;
        float v3 = (j4 + 3 <= i) ? s4.w : -INFINITY;
        float mx = fmaxf(fmaxf(v0, v1), fmaxf(v2, v3));
        if (mx > m) { l *= __expf(m - mx); m = mx; }
        l += __expf(v0 - m) + __expf(v1 - m) + __expf(v2 - m) + __expf(v3 - m);
    }
    __shared__ float sm[256], sl[256];
    sm[tid] = m; sl[tid] = l;
    __syncthreads();
    for (int s = 128; s > 0; s >>= 1) {
        if (tid < s) {
            float m1 = sm[tid], l1 = sl[tid];
            float m2 = sm[tid + s], l2 = sl[tid + s];
            float M = fmaxf(m1, m2);
            float L = (M == -INFINITY) ? 0.f
                      : l1 * __expf(m1 - M) + l2 * __expf(m2 - M);
            sm[tid] = M; sl[tid] = L;
        }
        __syncthreads();
    }
    if (tid == 0) { g_m[g * NSEQ + i] = sm[0]; g_l[g * NSEQ + i] = sl[0]; }
}

// ---------------- softmax + post-mix -> attn bf16 hi/lo (2 j / thread) ------
__global__ __launch_bounds__(256) void postmix_k(const float* __restrict__ Wpost)
{
    __shared__ float w[256], sm_[16], sl_[16];
    int tid = threadIdx.x;
    int i = blockIdx.y;
    w[tid] = Wpost[tid];
    if (tid < 16) {
        sm_[tid] = g_m[tid * NSEQ + i];
        sl_[tid] = 1.f / g_l[tid * NSEQ + i];
    }
    __syncthreads();
    int j = blockIdx.x * 512 + tid * 2;
    if (j > i) return;
    bool two = (j + 1 <= i);

    float a0[16], a1[16];
    #pragma unroll
    for (int h = 0; h < 16; h++) {
        float2 s = *(const float2*)&g_S[(size_t)(h * NSEQ + i) * NSEQ + j];
        a0[h] = __expf(s.x - sm_[h]) * sl_[h];
        a1[h] = two ? __expf(s.y - sm_[h]) * sl_[h] : 0.f;
    }
    #pragma unroll
    for (int g = 0; g < 16; g++) {
        float v0 = 0.f, v1 = 0.f;
        #pragma unroll
        for (int h = 0; h < 16; h++) {
            float wg = w[g * 16 + h];
            v0 = fmaf(wg, a0[h], v0);
            v1 = fmaf(wg, a1[h], v1);
        }
        size_t idx = (size_t)(g * NSEQ + i) * NSEQ + j;
        bf16 h0 = __float2bfloat16(v0);
        bf16 h1 = __float2bfloat16(v1);
        if (two) {
            __nv_bfloat162 hi, lo;
            hi.x = h0; hi.y = h1;
            lo.x = __float2bfloat16(v0 - __bfloat162float(h0));
            lo.y = __float2bfloat16(v1 - __bfloat162float(h1));
            *(__nv_bfloat162*)&g_Shi[idx] = hi;
            *(__nv_bfloat162*)&g_Slo[idx] = lo;
        } else {
            g_Shi[idx] = h0;
            g_Slo[idx] = __float2bfloat16(v0 - __bfloat162float(h0));
        }
    }
}

// ---------------- HMMA attn @ V (2-stage cp.async) -> bf16 hi/lo ------------
#define TSTR 72
#define AV_SPL (64 * TSTR * 2)                 // 9216 bytes per array
#define AV_STAGE (4 * AV_SPL)                  // 36864
#define AV_SMEM (2 * AV_STAGE)                 // 73728

#define AV2_ISSUE(j0_, stg) do {                                            \
    uint32_t s_ = sbase + (stg) * AV_STAGE;                                 \
    _Pragma("unroll")                                                       \
    for (int l_ = 0; l_ < 4; l_++) {                                        \
        int idx_ = tid + l_ * 128;                                          \
        int r_ = idx_ >> 3, c_ = (idx_ & 7) * 8;                            \
        uint32_t so_ = s_ + r_ * (TSTR * 2) + c_ * 2;                       \
        size_t ga_ = (size_t)(h * NSEQ + i0 + r_) * NSEQ + (j0_) + c_;      \
        size_t gb_ = (size_t)(h * DD + r_) * NSEQ + (j0_) + c_;             \
        cp16(so_,              g_Shi + ga_);                                \
        cp16(so_ + AV_SPL,     g_Slo + ga_);                                \
        cp16(so_ + 2 * AV_SPL, g_vthi + gb_);                               \
        cp16(so_ + 3 * AV_SPL, g_vtlo + gb_);                               \
    }                                                                       \
    asm volatile("cp.async.commit_group;" ::: "memory");                    \
} while (0)

__global__ __launch_bounds__(128) void av2_k(const float* __restrict__ bpost)
{
    extern __shared__ __align__(16) char avsm[];
    uint32_t sbase = smem_u32(avsm);

    int it = blockIdx.x, h = blockIdx.y;
    int i0 = it * 64;
    int tid = threadIdx.x, lane = tid & 31, wid = tid >> 5;
    int tq = lane >> 2, tk = (lane & 3) * 2;
    int m = wid * 16;

    uint32_t a_lane = ((lane & 15) * TSTR + (lane >> 4) * 8) * 2;
    uint32_t b_lane = (((lane & 7) + ((lane >> 4) << 3)) * TSTR
                       + ((lane >> 3) & 1) * 8) * 2;

    float acc[8][4] = {};
    int ntiles = it + 1;

    AV2_ISSUE(0, 0);
    for (int t = 0; t < ntiles; t++) {
        if (t + 1 < ntiles) {
            AV2_ISSUE((t + 1) * 64, (t + 1) & 1);
            asm volatile("cp.async.wait_group 1;" ::: "memory");
        } else {
            asm volatile("cp.async.wait_group 0;" ::: "memory");
        }
        __syncthreads();

        uint32_t stg = sbase + (t & 1) * AV_STAGE;
        bf16* Ah = (bf16*)(avsm + (t & 1) * AV_STAGE);
        bf16* Al = Ah + 64 * TSTR;

        if (t == it) {   // diagonal tile: zero upper triangle (j > i)
            bf16 z = __float2bfloat16(0.f);
            #pragma unroll 8
            for (int l = 0; l < 32; l++) {
                int idx = tid + l * 128;
                int r = idx >> 6, c = idx & 63;
                if (c > r) { Ah[r * TSTR + c] = z; Al[r * TSTR + c] = z; }
            }
            __syncthreads();
        }

        #pragma unroll
        for (int ki = 0; ki < 4; ki++) {
            uint32_t koff = ki * 32;
            uint32_t ah[4], al[4];
            ldsm_x4(ah, stg + (uint32_t)(m * TSTR * 2) + koff + a_lane);
            ldsm_x4(al, stg + AV_SPL + (uint32_t)(m * TSTR * 2) + koff + a_lane);
            uint32_t bhf[8][2], blf[8][2];
            #pragma unroll
            for (int np = 0; np < 4; np++) {
                uint32_t boff = (uint32_t)(np * 16 * TSTR * 2) + koff + b_lane;
                uint32_t r[4];
                ldsm_x4(r, stg + 2 * AV_SPL + boff);
                bhf[2 * np][0] = r[0]; bhf[2 * np][1] = r[1];
                bhf[2 * np + 1][0] = r[2]; bhf[2 * np + 1][1] = r[3];
                ldsm_x4(r, stg + 3 * AV_SPL + boff);
                blf[2 * np][0] = r[0]; blf[2 * np][1] = r[1];
                blf[2 * np + 1][0] = r[2]; blf[2 * np + 1][1] = r[3];
            }
            #pragma unroll
            for (int n = 0; n < 8; n++) {
                mma_bf16(acc[n], ah, bhf[n]);
                mma_bf16(acc[n], al, bhf[n]);
                mma_bf16(acc[n], ah, blf[n]);
            }
        }
        __syncthreads();
    }

    float bpv = bpost[h];
    int row = i0 + m + tq;
    #pragma unroll
    for (int n = 0; n < 8; n++) {
        int d = n * 8 + tk;
        float s0 = bpv * g_sumv[h * DD + d];
        float s1 = bpv * g_sumv[h * DD + d + 1];
        float v00 = acc[n][0] + s0, v01 = acc[n][1] + s1;
        float v10 = acc[n][2] + s0, v11 = acc[n][3] + s1;
        size_t o0 = (size_t)row * CDIM + h * DD + d;
        size_t o1 = (size_t)(row + 8) * CDIM + h * DD + d;
        __nv_bfloat162 hi0, hi1, lo0, lo1;
        hi0.x = __float2bfloat16(v00); hi0.y = __float2bfloat16(v01);
        hi1.x = __float2bfloat16(v10); hi1.y = __float2bfloat16(v11);
        lo0.x = __float2bfloat16(v00 - __bfloat162float(hi0.x));
        lo0.y = __float2bfloat16(v01 - __bfloat162float(hi0.y));
        lo1.x = __float2bfloat16(v10 - __bfloat162float(hi1.x));
        lo1.y = __float2bfloat16(v11 - __bfloat162float(hi1.y));
        *(__nv_bfloat162*)&g_ahi[o0] = hi0;
        *(__nv_bfloat162*)&g_ahi[o1] = hi1;
        *(__nv_bfloat162*)&g_alo[o0] = lo0;
        *(__nv_bfloat162*)&g_alo[o1] = lo1;
    }
}

// ---------------- launch -----------------------------------------------------
extern "C" void kernel_launch(void* const* d_in, const int* in_sizes, int n_in,
                              void* d_out, int out_size)
{
    const float* x     = (const float*)d_in[0];
    const float* pb    = (const float*)d_in[1];
    // d_in[2] = mask: causal, applied analytically
    const float* Wqkv  = (const float*)d_in[3];
    const float* Wout  = (const float*)d_in[4];
    const float* temp  = (const float*)d_in[5];
    const float* Wpre  = (const float*)d_in[6];
    const float* bpre  = (const float*)d_in[7];
    const float* Wpost = (const float*)d_in[8];
    const float* bpost = (const float*)d_in[9];

    float* out  = (float*)d_out;                 // [2048, 1024]
    float* kout = out + NSEQ * CDIM;             // kv[0] = k  [16,2048,64]
    float* vout = kout + HH * NSEQ * DD;         // kv[1] = v

    cudaFuncSetAttribute(hmma_gemm,
        cudaFuncAttributeMaxDynamicSharedMemorySize, GEMM_SMEM);
    cudaFuncSetAttribute(av2_k,
        cudaFuncAttributeMaxDynamicSharedMemorySize, AV_SMEM);

    void* p_qkv;
    cudaGetSymbolAddress(&p_qkv, g_qkv);
    void *p_xhi, *p_xlo, *p_whi, *p_wlo, *p_ohi, *p_olo, *p_ahi, *p_alo;
    cudaGetSymbolAddress(&p_xhi, g_xhi); cudaGetSymbolAddress(&p_xlo, g_xlo);
    cudaGetSymbolAddress(&p_whi, g_whi); cudaGetSymbolAddress(&p_wlo, g_wlo);
    cudaGetSymbolAddress(&p_ohi, g_ohi); cudaGetSymbolAddress(&p_olo, g_olo);
    cudaGetSymbolAddress(&p_ahi, g_ahi); cudaGetSymbolAddress(&p_alo, g_alo);

    // 0. bf16 hi/lo splits of x, W_qkv, W_out
    conv_split<<<(NSEQ * CDIM) / 256, 256>>>(x, (bf16*)p_xhi, (bf16*)p_xlo,
                                             NSEQ * CDIM);
    conv_split<<<(FDIM * CDIM) / 256, 256>>>(Wqkv, (bf16*)p_whi, (bf16*)p_wlo,
                                             FDIM * CDIM);
    conv_split<<<(CDIM * CDIM) / 256, 256>>>(Wout, (bf16*)p_ohi, (bf16*)p_olo,
                                             CDIM * CDIM);

    // 1. qkv = x @ W_qkv^T  (3-stage pipelined HMMA bf16x3 + ldmatrix)
    hmma_gemm<<<dim3(FDIM / 128, NSEQ / 128), 256, GEMM_SMEM>>>(
        (const bf16*)p_xhi, (const bf16*)p_xlo,
        (const bf16*)p_whi, (const bf16*)p_wlo, (float*)p_qkv, CDIM, FDIM);

    // 2. split + l2norm -> bf16 hi/lo; kv outputs
    split_norm<<<dim3(NSEQ, HH), 64>>>(kout, vout);
    // 3. V transpose -> bf16 hi/lo [h][d][n]; sum_j v
    transpose_v<<<dim3(NSEQ / 32, DD / 32, HH), 256>>>(vout);
    sumv_k<<<HH, 256>>>(vout);
    // 4. fused dots(16 heads) + premix + pos_bias -> premixed S
    dots16_k<<<dim3(NSEQ / 32, NSEQ / 32), 256>>>(Wpre, bpre, pb, temp);
    // 5. row max / sum-exp (float4)
    rowstat_k<<<dim3(NSEQ, HH), 256>>>();
    // 6. softmax + post-mix -> attn bf16 hi/lo (2 j / thread)
    postmix_k<<<dim3(NSEQ / 512, NSEQ), 256>>>(Wpost);
    // 7. attn @ V (2-stage pipelined HMMA + ldmatrix) -> bf16 hi/lo directly
    av2_k<<<dim3(NSEQ / 64, HH), 128, AV_SMEM>>>(bpost);

    // 8. out = oa @ W_out^T  (3-stage pipelined HMMA bf16x3 + ldmatrix)
    hmma_gemm<<<dim3(CDIM / 128, NSEQ / 128), 256, GEMM_SMEM>>>(
        (const bf16*)p_ahi, (const bf16*)p_alo,
        (const bf16*)p_ohi, (const bf16*)p_olo, out, CDIM, CDIM);
}